// round 4
// baseline (speedup 1.0000x reference)
#include <cuda_runtime.h>

// ---------------------------------------------------------------------------
// Problem constants
// ---------------------------------------------------------------------------
#define BATCH 16
#define CIN   512
#define CMID  256
#define HIN   32
#define WIN   32
#define HOUT  64
#define WOUT  64
#define KC    8                  // cin chunk staged through smem
#define NOUT  (BATCH * CMID * HOUT * WOUT)   // 16,777,216

// ---------------------------------------------------------------------------
// Scratch (no allocations allowed -> __device__ globals)
// ---------------------------------------------------------------------------
__device__ float g_Y1[NOUT];     // branch-1 interleaved conv output (pre-BN)
__device__ float g_Y2[NOUT];     // branch-2 interleaved conv output (pre-BN)
__device__ float g_O1[NOUT];     // conv9 output (pre-BN)
__device__ float g_a1[CMID], g_s1[CMID];   // BN11 folded affine (for conv9 input)
__device__ float g_a2[CMID], g_s2[CMID];   // BN12 folded affine (branch 2)
__device__ float g_a3[CMID], g_s3[CMID];   // BN2  folded affine (conv9 output)

// ---------------------------------------------------------------------------
// Fused "unpool-as-conv" kernel: one of the 4 conv shapes, both branches.
//   out(i,j) = bias + sum_{kh,kw} w[kh][kw] * x[i+kh-1, j+kw-1]   (zero pad)
// written interleaved into Y at (2i+qr, 2j+qc).
// Tiling: 128 couts x (4 rows x 32 cols = 128 pixels), 256 threads,
// each thread 8 couts x 8 pixels.
// ---------------------------------------------------------------------------
template <int KH, int KW>
__global__ __launch_bounds__(256, 2)
void conv_unpool_kernel(const float* __restrict__ x,
                        const float* __restrict__ w_b0, const float* __restrict__ b_b0,
                        const float* __restrict__ w_b1, const float* __restrict__ b_b1,
                        int qr, int qc)
{
    constexpr int TAPS = KH * KW;
    constexpr int F4PC = (KC * TAPS) / 4;       // float4 per cout per chunk

    __shared__ float sx[KC][6][34];             // input tile + halo (stride 34: conflict-free)
    __shared__ float sw[KC][TAPS][128];         // weights [cin][tap][cout]

    const int tid = threadIdx.x;
    const int tx  = tid & 15;                   // pixel group
    const int ty  = tid >> 4;                   // cout group
    const int co0 = blockIdx.x * 128;
    const int r0  = blockIdx.y * 4;
    const int n   = blockIdx.z & 15;
    const int branch = blockIdx.z >> 4;

    const float* Wm = branch ? w_b1 : w_b0;
    const float* Bv = branch ? b_b1 : b_b0;
    float*       Y  = branch ? g_Y2 : g_Y1;

    const int lr = tx >> 2;                     // local row 0..3
    const int cb = (tx & 3) * 8;                // local col base 0,8,16,24

    float acc[8][8];
#pragma unroll
    for (int c = 0; c < 8; ++c)
#pragma unroll
        for (int u = 0; u < 8; ++u) acc[c][u] = 0.0f;

    const float* xn = x + (size_t)n * CIN * (HIN * WIN);

    for (int chunk = 0; chunk < CIN / KC; ++chunk) {
        const int c0 = chunk * KC;

        // ---- stage input tile (rows r0-1..r0+4, cols -1..32, zero padded) ----
        for (int idx = tid; idx < KC * 6 * 34; idx += 256) {
            int ci  = idx / 204;
            int rem = idx - ci * 204;
            int rr  = rem / 34;
            int cc  = rem - rr * 34;
            int gr  = r0 + rr - 1;
            int gc  = cc - 1;
            float v = 0.0f;
            if ((unsigned)gr < (unsigned)HIN && (unsigned)gc < (unsigned)WIN)
                v = xn[(c0 + ci) * (HIN * WIN) + gr * WIN + gc];
            sx[ci][rr][cc] = v;
        }

        // ---- stage weights: gmem [cout][cin][kh][kw] -> smem [cin][tap][cout] ----
        for (int f = tid; f < 128 * F4PC; f += 256) {
            int co = f / F4PC;
            int rp = f - co * F4PC;
            const float4 v = *reinterpret_cast<const float4*>(
                Wm + ((size_t)(co0 + co) * CIN + c0) * TAPS + rp * 4);
            float vv[4] = {v.x, v.y, v.z, v.w};
            int lin = rp * 4;
#pragma unroll
            for (int k = 0; k < 4; ++k) {
                int ci = (lin + k) / TAPS;
                int t  = (lin + k) % TAPS;
                sw[ci][t][co] = vv[k];
            }
        }
        __syncthreads();

        // ---- compute ----
#pragma unroll
        for (int ci = 0; ci < KC; ++ci) {
#pragma unroll
            for (int kh = 0; kh < KH; ++kh) {
#pragma unroll
                for (int kw = 0; kw < KW; ++kw) {
                    const float4 wa = *reinterpret_cast<const float4*>(&sw[ci][kh * KW + kw][ty * 8]);
                    const float4 wb = *reinterpret_cast<const float4*>(&sw[ci][kh * KW + kw][ty * 8 + 4]);
#pragma unroll
                    for (int u = 0; u < 8; ++u) {
                        const float xv = sx[ci][lr + kh][cb + kw + u];
                        acc[0][u] = fmaf(wa.x, xv, acc[0][u]);
                        acc[1][u] = fmaf(wa.y, xv, acc[1][u]);
                        acc[2][u] = fmaf(wa.z, xv, acc[2][u]);
                        acc[3][u] = fmaf(wa.w, xv, acc[3][u]);
                        acc[4][u] = fmaf(wb.x, xv, acc[4][u]);
                        acc[5][u] = fmaf(wb.y, xv, acc[5][u]);
                        acc[6][u] = fmaf(wb.z, xv, acc[6][u]);
                        acc[7][u] = fmaf(wb.w, xv, acc[7][u]);
                    }
                }
            }
        }
        __syncthreads();
    }

    // ---- epilogue: bias + interleaved store ----
    const int i = r0 + lr;
#pragma unroll
    for (int c = 0; c < 8; ++c) {
        const int co = co0 + ty * 8 + c;
        const float bv = Bv[co];
        float* dst = Y + ((size_t)(n * CMID + co) * HOUT + (2 * i + qr)) * WOUT + qc + 2 * cb;
#pragma unroll
        for (int u = 0; u < 8; ++u)
            dst[2 * u] = acc[c][u] + bv;
    }
}

// ---------------------------------------------------------------------------
// conv9: 3x3 pad 1, 256->256 on [16,256,64,64]; input = relu(BN11(g_Y1))
// folded as per-channel affine on load. Writes g_O1 (pre-BN).
// ---------------------------------------------------------------------------
__global__ __launch_bounds__(256, 2)
void conv9_kernel(const float* __restrict__ Wm, const float* __restrict__ Bv)
{
    __shared__ float sx[KC][6][34];
    __shared__ float sw[KC][9][128];

    const int tid = threadIdx.x;
    const int tx  = tid & 15;
    const int ty  = tid >> 4;
    const int co0 = blockIdx.x * 128;
    const int ry  = blockIdx.y >> 1;
    const int cxo = (blockIdx.y & 1) * 32;
    const int r0  = ry * 4;
    const int n   = blockIdx.z;

    const int lr = tx >> 2;
    const int cb = (tx & 3) * 8;

    float acc[8][8];
#pragma unroll
    for (int c = 0; c < 8; ++c)
#pragma unroll
        for (int u = 0; u < 8; ++u) acc[c][u] = 0.0f;

    const float* yn = g_Y1 + (size_t)n * CMID * (HOUT * WOUT);

    for (int chunk = 0; chunk < CMID / KC; ++chunk) {
        const int c0 = chunk * KC;

        for (int idx = tid; idx < KC * 6 * 34; idx += 256) {
            int ci  = idx / 204;
            int rem = idx - ci * 204;
            int rr  = rem / 34;
            int cc  = rem - rr * 34;
            int gr  = r0 + rr - 1;
            int gc  = cxo + cc - 1;
            float v = 0.0f;
            if ((unsigned)gr < (unsigned)HOUT && (unsigned)gc < (unsigned)WOUT) {
                const int ch = c0 + ci;
                const float yv = yn[ch * (HOUT * WOUT) + gr * WOUT + gc];
                v = fmaxf(0.0f, fmaf(yv, g_a1[ch], g_s1[ch]));   // BN11 + relu folded
            }
            sx[ci][rr][cc] = v;
        }

        for (int f = tid; f < 128 * 18; f += 256) {     // F4PC = (8*9)/4 = 18
            int co = f / 18;
            int rp = f - co * 18;
            const float4 v = *reinterpret_cast<const float4*>(
                Wm + ((size_t)(co0 + co) * CMID + c0) * 9 + rp * 4);
            float vv[4] = {v.x, v.y, v.z, v.w};
            int lin = rp * 4;
#pragma unroll
            for (int k = 0; k < 4; ++k) {
                int ci = (lin + k) / 9;
                int t  = (lin + k) % 9;
                sw[ci][t][co] = vv[k];
            }
        }
        __syncthreads();

#pragma unroll
        for (int ci = 0; ci < KC; ++ci) {
#pragma unroll
            for (int kh = 0; kh < 3; ++kh) {
#pragma unroll
                for (int kw = 0; kw < 3; ++kw) {
                    const float4 wa = *reinterpret_cast<const float4*>(&sw[ci][kh * 3 + kw][ty * 8]);
                    const float4 wb = *reinterpret_cast<const float4*>(&sw[ci][kh * 3 + kw][ty * 8 + 4]);
#pragma unroll
                    for (int u = 0; u < 8; ++u) {
                        const float xv = sx[ci][lr + kh][cb + kw + u];
                        acc[0][u] = fmaf(wa.x, xv, acc[0][u]);
                        acc[1][u] = fmaf(wa.y, xv, acc[1][u]);
                        acc[2][u] = fmaf(wa.z, xv, acc[2][u]);
                        acc[3][u] = fmaf(wa.w, xv, acc[3][u]);
                        acc[4][u] = fmaf(wb.x, xv, acc[4][u]);
                        acc[5][u] = fmaf(wb.y, xv, acc[5][u]);
                        acc[6][u] = fmaf(wb.z, xv, acc[6][u]);
                        acc[7][u] = fmaf(wb.w, xv, acc[7][u]);
                    }
                }
            }
        }
        __syncthreads();
    }

    const int i = r0 + lr;
#pragma unroll
    for (int c = 0; c < 8; ++c) {
        const int co = co0 + ty * 8 + c;
        const float bv = Bv[co];
        float* dst = g_O1 + ((size_t)(n * CMID + co) * HOUT + i) * WOUT + cxo + cb;
        float4 v0, v1;
        v0.x = acc[c][0] + bv; v0.y = acc[c][1] + bv; v0.z = acc[c][2] + bv; v0.w = acc[c][3] + bv;
        v1.x = acc[c][4] + bv; v1.y = acc[c][5] + bv; v1.z = acc[c][6] + bv; v1.w = acc[c][7] + bv;
        *reinterpret_cast<float4*>(dst)     = v0;
        *reinterpret_cast<float4*>(dst + 4) = v1;
    }
}

// ---------------------------------------------------------------------------
// BN batch-stats: one block per channel. which: 0 -> Y1/a1, 1 -> Y2/a2, 2 -> O1/a3.
// Computes a = gamma*rsqrt(var+eps), s = beta - mean*a  (biased var over N,H,W).
// ---------------------------------------------------------------------------
__global__ void bn_stats_kernel(int which,
                                const float* __restrict__ gamma,
                                const float* __restrict__ beta)
{
    const int ch  = blockIdx.x;
    const int tid = threadIdx.x;
    const float* y = (which == 0) ? g_Y1 : (which == 1) ? g_Y2 : g_O1;
    float* A = (which == 0) ? g_a1 : (which == 1) ? g_a2 : g_a3;
    float* S = (which == 0) ? g_s1 : (which == 1) ? g_s2 : g_s3;

    float sum = 0.0f, sq = 0.0f;
    // 16 batch planes of 4096 floats = 1024 float4 each
    for (int idx = tid; idx < BATCH * 1024; idx += 256) {
        const int nn = idx >> 10;
        const int e4 = idx & 1023;
        const float4 v = reinterpret_cast<const float4*>(
            y + (size_t)(nn * CMID + ch) * 4096)[e4];
        sum += v.x + v.y + v.z + v.w;
        sq  += v.x * v.x + v.y * v.y + v.z * v.z + v.w * v.w;
    }

    __shared__ float rs[256], rq[256];
    rs[tid] = sum; rq[tid] = sq;
    __syncthreads();
    for (int off = 128; off > 0; off >>= 1) {
        if (tid < off) { rs[tid] += rs[tid + off]; rq[tid] += rq[tid + off]; }
        __syncthreads();
    }
    if (tid == 0) {
        const float inv = 1.0f / (float)(BATCH * HOUT * WOUT);
        const float mean = rs[0] * inv;
        const float var  = rq[0] * inv - mean * mean;
        const float rstd = rsqrtf(var + 1e-5f);
        const float a = gamma[ch] * rstd;
        A[ch] = a;
        S[ch] = beta[ch] - mean * a;
    }
}

// ---------------------------------------------------------------------------
// Final merge: out = relu( BN2(O1) + BN12(Y2) ), vectorized float4.
// ---------------------------------------------------------------------------
__global__ void final_kernel(float* __restrict__ out)
{
    const int idx = blockIdx.x * blockDim.x + threadIdx.x;   // over NOUT/4
    if (idx >= NOUT / 4) return;
    const int c = (idx >> 10) & (CMID - 1);                  // 1024 float4 per channel plane
    const float a2 = g_a2[c], s2 = g_s2[c];
    const float a3 = g_a3[c], s3 = g_s3[c];
    const float4 o = reinterpret_cast<const float4*>(g_O1)[idx];
    const float4 y = reinterpret_cast<const float4*>(g_Y2)[idx];
    float4 r;
    r.x = fmaxf(0.0f, fmaf(o.x, a3, s3) + fmaf(y.x, a2, s2));
    r.y = fmaxf(0.0f, fmaf(o.y, a3, s3) + fmaf(y.y, a2, s2));
    r.z = fmaxf(0.0f, fmaf(o.z, a3, s3) + fmaf(y.z, a2, s2));
    r.w = fmaxf(0.0f, fmaf(o.w, a3, s3) + fmaf(y.w, a2, s2));
    reinterpret_cast<float4*>(out)[idx] = r;
}

// ---------------------------------------------------------------------------
// Launch: 4 fused conv launches (both branches each), stats, conv9, stats, merge
// ---------------------------------------------------------------------------
extern "C" void kernel_launch(void* const* d_in, const int* in_sizes, int n_in,
                              void* d_out, int out_size)
{
    const float* x   = (const float*)d_in[0];
    const float* w1  = (const float*)d_in[1];   const float* b1  = (const float*)d_in[2];
    const float* w2  = (const float*)d_in[3];   const float* b2  = (const float*)d_in[4];
    const float* w3  = (const float*)d_in[5];   const float* b3  = (const float*)d_in[6];
    const float* w4  = (const float*)d_in[7];   const float* b4  = (const float*)d_in[8];
    const float* w5  = (const float*)d_in[9];   const float* b5  = (const float*)d_in[10];
    const float* w6  = (const float*)d_in[11];  const float* b6  = (const float*)d_in[12];
    const float* w7  = (const float*)d_in[13];  const float* b7  = (const float*)d_in[14];
    const float* w8  = (const float*)d_in[15];  const float* b8  = (const float*)d_in[16];
    const float* w9  = (const float*)d_in[17];  const float* b9  = (const float*)d_in[18];
    const float* g11 = (const float*)d_in[19];  const float* be11 = (const float*)d_in[20];
    const float* g12 = (const float*)d_in[21];  const float* be12 = (const float*)d_in[22];
    const float* g2  = (const float*)d_in[23];  const float* be2  = (const float*)d_in[24];

    const dim3 gU(2, 8, 32);      // cout tiles x row tiles x (batch * branch)
    conv_unpool_kernel<3, 3><<<gU, 256>>>(x, w1, b1, w5, b5, 0, 0);  // A -> (2i,   2j)
    conv_unpool_kernel<2, 3><<<gU, 256>>>(x, w2, b2, w6, b6, 1, 0);  // B -> (2i+1, 2j)
    conv_unpool_kernel<3, 2><<<gU, 256>>>(x, w3, b3, w7, b7, 0, 1);  // C -> (2i,   2j+1)
    conv_unpool_kernel<2, 2><<<gU, 256>>>(x, w4, b4, w8, b8, 1, 1);  // D -> (2i+1, 2j+1)

    bn_stats_kernel<<<CMID, 256>>>(0, g11, be11);   // BN11 affine (folded into conv9 load)
    bn_stats_kernel<<<CMID, 256>>>(1, g12, be12);   // BN12 affine (folded into final)

    conv9_kernel<<<dim3(2, 32, 16), 256>>>(w9, b9);

    bn_stats_kernel<<<CMID, 256>>>(2, g2, be2);     // BN2 affine (folded into final)

    final_kernel<<<(NOUT / 4 + 255) / 256, 256>>>((float*)d_out);
}

// round 6
// speedup vs baseline: 3.1656x; 3.1656x over previous
#include <cuda_runtime.h>
#include <cuda_bf16.h>
#include <cstdint>

// ---------------------------------------------------------------------------
// Problem constants
// ---------------------------------------------------------------------------
#define BATCH 16
#define CIN   512
#define CMID  256
#define HOUT  64
#define WOUT  64
#define NOUT  (BATCH * CMID * HOUT * WOUT)   // 16,777,216

// ---------------------------------------------------------------------------
// Device-global scratch (no allocations allowed)
// ---------------------------------------------------------------------------
__device__ float g_Y1[NOUT];                 // branch-1 interleaved output (pre-BN)
__device__ float g_Y2[NOUT];                 // branch-2 interleaved output
__device__ float g_O1[NOUT];                 // conv9 output (pre-BN)
__device__ float g_a1[CMID], g_s1[CMID];
__device__ float g_a2[CMID], g_s2[CMID];
__device__ float g_a3[CMID], g_s3[CMID];
__device__ float g_biasAll[2048];

// Padded, channel-innermost activations (bf16 hi/lo split)
__device__ __nv_bfloat16 g_Xp_hi [BATCH * 34 * 34 * CIN];
__device__ __nv_bfloat16 g_Xp_lo [BATCH * 34 * 34 * CIN];
__device__ __nv_bfloat16 g_X2p_hi[BATCH * 66 * 66 * CMID];
__device__ __nv_bfloat16 g_X2p_lo[BATCH * 66 * 66 * CMID];

// Tap-major weights: [tap][M][Cin]  (all convs zero-padded to 3x3)
__device__ __nv_bfloat16 g_Wb_hi[9 * 2048 * CIN];
__device__ __nv_bfloat16 g_Wb_lo[9 * 2048 * CIN];
__device__ __nv_bfloat16 g_W9_hi[9 * 256 * CMID];
__device__ __nv_bfloat16 g_W9_lo[9 * 256 * CMID];

// ---------------------------------------------------------------------------
// Helpers (all base sm_80+ features — valid on plain sm_103 target)
// ---------------------------------------------------------------------------
__device__ __forceinline__ uint32_t smem_u32(const void* p) {
    uint32_t a;
    asm("{ .reg .u64 t; cvta.to.shared.u64 t, %1; cvt.u32.u64 %0, t; }" : "=r"(a) : "l"(p));
    return a;
}
__device__ __forceinline__ uint32_t sw128(uint32_t off) { return off ^ ((off >> 3) & 0x70); }

#define CP16(saddr, gptr) \
    asm volatile("cp.async.cg.shared.global [%0], [%1], 16;" :: "r"(saddr), "l"(gptr))
#define CP_COMMIT() asm volatile("cp.async.commit_group;" ::: "memory")
#define CP_WAIT1()  asm volatile("cp.async.wait_group 1;" ::: "memory")

#define LDSM4(r0, r1, r2, r3, addr) \
    asm volatile("ldmatrix.sync.aligned.m8n8.x4.shared.b16 {%0,%1,%2,%3}, [%4];" \
                 : "=r"(r0), "=r"(r1), "=r"(r2), "=r"(r3) : "r"(addr))

#define MMA_BF16(d, a, b) \
    asm volatile("mma.sync.aligned.m16n8k16.row.col.f32.bf16.bf16.f32 " \
                 "{%0,%1,%2,%3}, {%4,%5,%6,%7}, {%8,%9}, {%0,%1,%2,%3};" \
                 : "+f"((d)[0]), "+f"((d)[1]), "+f"((d)[2]), "+f"((d)[3]) \
                 : "r"((a)[0]), "r"((a)[1]), "r"((a)[2]), "r"((a)[3]),   \
                   "r"((b)[0]), "r"((b)[1]))

// ---------------------------------------------------------------------------
// Pre-pass: pad + transpose to channel-innermost + bf16 hi/lo split.
// AFFINE=false: src = x (fp32 NCHW) -> g_Xp.  AFFINE=true: src = g_Y1 with
// relu(BN11) folded -> g_X2p.  Border cells written as zeros.
// ---------------------------------------------------------------------------
template <int C, int H, bool AFFINE>
__global__ void pad_transpose_kernel(const float* __restrict__ src_arg)
{
    constexpr int HP = H + 2, WP = H + 2;
    constexpr int CB = C / 64;
    __shared__ float sm[64][H + 1];

    const int bid = blockIdx.x;
    const int cb  = bid % CB;
    const int y   = (bid / CB) % HP;
    const int img = bid / (CB * HP);
    const int tid = threadIdx.x;

    const float* src = AFFINE ? (const float*)g_Y1 : src_arg;
    __nv_bfloat16* oh = (AFFINE ? g_X2p_hi : g_Xp_hi) + ((size_t)(img * HP + y)) * WP * C + cb * 64;
    __nv_bfloat16* ol = (AFFINE ? g_X2p_lo : g_Xp_lo) + ((size_t)(img * HP + y)) * WP * C + cb * 64;

    if (y == 0 || y == HP - 1) {
        for (int t = tid; t < WP * 64; t += 256) {
            int x = t >> 6, ci = t & 63;
            oh[(size_t)x * C + ci] = __float2bfloat16_rn(0.0f);
            ol[(size_t)x * C + ci] = __float2bfloat16_rn(0.0f);
        }
        return;
    }

    for (int t = tid; t < 64 * H; t += 256) {
        int ci = t / H, x = t % H;
        int ch = cb * 64 + ci;
        float v = src[((size_t)(img * C + ch) * H + (y - 1)) * H + x];
        if (AFFINE) v = fmaxf(0.0f, fmaf(v, g_a1[ch], g_s1[ch]));
        sm[ci][x] = v;
    }
    __syncthreads();

    for (int t = tid; t < WP * 64; t += 256) {
        int x = t >> 6, ci = t & 63;
        float v = (x >= 1 && x <= H) ? sm[ci][x - 1] : 0.0f;
        __nv_bfloat16 h = __float2bfloat16_rn(v);
        float lo = v - __bfloat162float(h);
        oh[(size_t)x * C + ci] = h;
        ol[(size_t)x * C + ci] = __float2bfloat16_rn(lo);
    }
}

// ---------------------------------------------------------------------------
// Pre-pass: 8 conv weight tensors -> tap-major zero-padded-3x3 bf16 hi/lo,
// plus flattened bias table.
// ---------------------------------------------------------------------------
__global__ void prep_weights_kernel(
    const float* __restrict__ w0, const float* __restrict__ w1,
    const float* __restrict__ w2, const float* __restrict__ w3,
    const float* __restrict__ w4, const float* __restrict__ w5,
    const float* __restrict__ w6, const float* __restrict__ w7,
    const float* __restrict__ b0, const float* __restrict__ b1,
    const float* __restrict__ b2, const float* __restrict__ b3,
    const float* __restrict__ b4, const float* __restrict__ b5,
    const float* __restrict__ b6, const float* __restrict__ b7)
{
    const int idx = blockIdx.x * 256 + threadIdx.x;   // 9*2048*512 elements
    const float* W[8] = {w0, w1, w2, w3, w4, w5, w6, w7};
    const float* B[8] = {b0, b1, b2, b3, b4, b5, b6, b7};
    const int KH[8] = {3, 2, 3, 2, 3, 2, 3, 2};
    const int KW[8] = {3, 3, 2, 2, 3, 3, 2, 2};

    if (idx < 2048) g_biasAll[idx] = B[idx >> 8][idx & 255];
    if (idx >= 9 * 2048 * 512) return;

    const int ci  = idx & 511;
    const int m   = (idx >> 9) & 2047;
    const int tap = idx >> 20;
    const int conv = m >> 8, co = m & 255;
    const int kh = tap / 3, kw = tap % 3;

    float v = 0.0f;
    if (kh < KH[conv] && kw < KW[conv])
        v = W[conv][((size_t)(co * CIN + ci) * KH[conv] + kh) * KW[conv] + kw];

    __nv_bfloat16 h = __float2bfloat16_rn(v);
    g_Wb_hi[idx] = h;
    g_Wb_lo[idx] = __float2bfloat16_rn(v - __bfloat162float(h));
}

__global__ void prep_w9_kernel(const float* __restrict__ w9)
{
    const int idx = blockIdx.x * 256 + threadIdx.x;   // 9*256*256
    if (idx >= 9 * 256 * 256) return;
    const int ci = idx & 255;
    const int co = (idx >> 8) & 255;
    const int tap = idx >> 16;
    const int kh = tap / 3, kw = tap % 3;
    float v = w9[((size_t)(co * CMID + ci) * 3 + kh) * 3 + kw];
    __nv_bfloat16 h = __float2bfloat16_rn(v);
    g_W9_hi[idx] = h;
    g_W9_lo[idx] = __float2bfloat16_rn(v - __bfloat162float(h));
}

// ---------------------------------------------------------------------------
// mma.sync implicit-conv GEMM, bf16 hi/lo 3-product split, fp32 accumulate.
// CTA tile 128(M) x 128(N pixels), warp tile 64x32, K chunked by 64 channels
// at a fixed tap (9*CIN_T/64 chunks), cp.async 2-stage double buffer.
// PHASE2=false: A=g_Wb (M=2048), B=g_Xp, epilogue interleaves into Y1/Y2.
// PHASE2=true : A=g_W9 (M=256),  B=g_X2p, epilogue -> g_O1 (+b9).
// ---------------------------------------------------------------------------
template <int CIN_T, int WDIM, int ROWS, int MTOT, bool PHASE2>
__global__ __launch_bounds__(256, 1)
void gemm_kernel(const float* __restrict__ bias9)
{
    constexpr int HP = WDIM + 2, WP = WDIM + 2;
    constexpr int NT_PER_IMG = (WDIM * WDIM) / 128;
    constexpr int KCH = CIN_T / 64;
    constexpr int NCHUNK = 9 * KCH;
    constexpr int CI_SHIFT = (WDIM == 32) ? 5 : 6;
    // smem per buffer: AH(16K) AL(16K) BH(16K) BL(16K) = 64KB; two buffers.
    constexpr uint32_t BUF = 65536;

    extern __shared__ char smem[];
    const uint32_t sb = smem_u32(smem);

    const int tid  = threadIdx.x;
    const int wid  = tid >> 5;
    const int lane = tid & 31;
    const int m0   = blockIdx.x * 128;
    const int img  = blockIdx.y / NT_PER_IMG;
    const int i0   = (blockIdx.y % NT_PER_IMG) * ROWS;

    const float4* A4h = reinterpret_cast<const float4*>(PHASE2 ? g_W9_hi : g_Wb_hi);
    const float4* A4l = reinterpret_cast<const float4*>(PHASE2 ? g_W9_lo : g_Wb_lo);
    const float4* B4h = reinterpret_cast<const float4*>(PHASE2 ? g_X2p_hi : g_Xp_hi);
    const float4* B4l = reinterpret_cast<const float4*>(PHASE2 ? g_X2p_lo : g_Xp_lo);

    // ---- staging: 16 cp.async x 16B per thread per chunk ----
    auto stage = [&](int chunk, int buf) {
        const int tap = chunk / KCH;
        const int ci0 = (chunk - tap * KCH) * 64;
        const int kh = tap / 3, kw = tap - kh * 3;
        const uint32_t bb = sb + buf * BUF;
#pragma unroll
        for (int it = 0; it < 4; ++it) {
            const int t = tid + it * 256;
            const int row = t >> 3, g = t & 7;
            const uint32_t off = sw128(row * 128 + g * 16);
            const long srcA = ((((long)(tap * MTOT + m0 + row) * CIN_T + ci0)) >> 3) + g;
            CP16(bb + off,         A4h + srcA);
            CP16(bb + 16384 + off, A4l + srcA);
            const int r = row >> CI_SHIFT, j = row & (WDIM - 1);
            const int y = i0 + r + kh, x = j + kw;
            const long srcB = ((((long)((img * HP + y) * WP + x) * CIN_T + ci0)) >> 3) + g;
            CP16(bb + 32768 + off, B4h + srcB);
            CP16(bb + 49152 + off, B4l + srcB);
        }
    };

    // ---- per-lane ldmatrix addressing components ----
    const int sub = lane >> 3, r8 = lane & 7;
    const int wm = wid & 1, wn = wid >> 1;
    const int arow_b = wm * 64 + ((sub & 1) << 3) + r8;   // + mt*16
    const int akoff  = (sub >> 1) << 4;
    const int brow_b = wn * 32 + ((sub >> 1) << 3) + r8;  // + q*16
    const int bkoff  = (sub & 1) << 4;

    float acc[4][4][4];
#pragma unroll
    for (int a = 0; a < 4; ++a)
#pragma unroll
        for (int b = 0; b < 4; ++b)
#pragma unroll
            for (int c = 0; c < 4; ++c) acc[a][b][c] = 0.0f;

    auto compute = [&](int buf) {
        const uint32_t AH = sb + buf * BUF;
        const uint32_t AL = AH + 16384, BH = AH + 32768, BL = AH + 49152;
#pragma unroll
        for (int kk = 0; kk < 4; ++kk) {
            uint32_t ah[4][4], al[4][4], bh[4][2], bl[4][2];
            // A_hi fragments (4 M tiles)
#pragma unroll
            for (int mt = 0; mt < 4; ++mt) {
                const uint32_t ad = AH + sw128((arow_b + mt * 16) * 128 + kk * 32 + akoff);
                LDSM4(ah[mt][0], ah[mt][1], ah[mt][2], ah[mt][3], ad);
            }
            // B_hi fragments (4 n8 tiles via 2 x4 loads)
#pragma unroll
            for (int q = 0; q < 2; ++q) {
                const uint32_t ad = BH + sw128((brow_b + q * 16) * 128 + kk * 32 + bkoff);
                LDSM4(bh[2 * q][0], bh[2 * q][1], bh[2 * q + 1][0], bh[2 * q + 1][1], ad);
            }
            // hh
#pragma unroll
            for (int mt = 0; mt < 4; ++mt)
#pragma unroll
                for (int nt = 0; nt < 4; ++nt)
                    MMA_BF16(acc[mt][nt], ah[mt], bh[nt]);
            // B_lo, hl
#pragma unroll
            for (int q = 0; q < 2; ++q) {
                const uint32_t ad = BL + sw128((brow_b + q * 16) * 128 + kk * 32 + bkoff);
                LDSM4(bl[2 * q][0], bl[2 * q][1], bl[2 * q + 1][0], bl[2 * q + 1][1], ad);
            }
#pragma unroll
            for (int mt = 0; mt < 4; ++mt)
#pragma unroll
                for (int nt = 0; nt < 4; ++nt)
                    MMA_BF16(acc[mt][nt], ah[mt], bl[nt]);
            // A_lo, lh
#pragma unroll
            for (int mt = 0; mt < 4; ++mt) {
                const uint32_t ad = AL + sw128((arow_b + mt * 16) * 128 + kk * 32 + akoff);
                LDSM4(al[mt][0], al[mt][1], al[mt][2], al[mt][3], ad);
            }
#pragma unroll
            for (int mt = 0; mt < 4; ++mt)
#pragma unroll
                for (int nt = 0; nt < 4; ++nt)
                    MMA_BF16(acc[mt][nt], al[mt], bh[nt]);
        }
    };

    // ---- 2-stage pipeline ----
    stage(0, 0); CP_COMMIT();
    stage(1, 1); CP_COMMIT();
    for (int c = 0; c < NCHUNK; ++c) {
        CP_WAIT1();
        __syncthreads();
        compute(c & 1);
        __syncthreads();
        if (c + 2 < NCHUNK) stage(c + 2, c & 1);
        CP_COMMIT();
    }

    // ---- epilogue: scatter fragments to gmem with folded interleave ----
    const float* bias = PHASE2 ? bias9 : g_biasAll;
    int qr = 0, qc = 0, coBase = m0;
    float* Ybuf = g_O1;
    if (!PHASE2) {
        const int conv = m0 >> 8;
        const int quad = conv & 3;
        qr = quad & 1;
        qc = (quad >> 1) & 1;
        coBase = m0 & 255;
        Ybuf = (conv >= 4) ? g_Y2 : g_Y1;
    }

#pragma unroll
    for (int mt = 0; mt < 4; ++mt) {
        const int rowA = wm * 64 + mt * 16 + (lane >> 2);
        const float bv0 = bias[m0 + rowA];
        const float bv8 = bias[m0 + rowA + 8];
        const int co0 = coBase + rowA;
#pragma unroll
        for (int nt = 0; nt < 4; ++nt) {
            const int p = wn * 32 + nt * 8 + 2 * (lane & 3);
            int yy, xx, xstep;
            if (!PHASE2) {
                const int pr = p >> 5, pc = p & 31;
                yy = 2 * (i0 + pr) + qr;
                xx = 2 * pc + qc;
                xstep = 2;
            } else {
                const int pr = p >> 6, pc = p & 63;
                yy = i0 + pr;
                xx = pc;
                xstep = 1;
            }
            float* base0 = Ybuf + ((size_t)(img * CMID + co0) * HOUT + yy) * WOUT + xx;
            float* base8 = base0 + (size_t)8 * HOUT * WOUT;
            base0[0]     = acc[mt][nt][0] + bv0;
            base0[xstep] = acc[mt][nt][1] + bv0;
            base8[0]     = acc[mt][nt][2] + bv8;
            base8[xstep] = acc[mt][nt][3] + bv8;
        }
    }
}

// ---------------------------------------------------------------------------
// BN batch stats (biased, over N,H,W) -> folded affine (a, s).
// ---------------------------------------------------------------------------
__global__ void bn_stats_kernel(int which,
                                const float* __restrict__ gamma,
                                const float* __restrict__ beta)
{
    const int ch  = blockIdx.x;
    const int tid = threadIdx.x;
    const float* y = (which == 0) ? g_Y1 : (which == 1) ? g_Y2 : g_O1;
    float* A = (which == 0) ? g_a1 : (which == 1) ? g_a2 : g_a3;
    float* S = (which == 0) ? g_s1 : (which == 1) ? g_s2 : g_s3;

    float sum = 0.0f, sq = 0.0f;
    for (int idx = tid; idx < BATCH * 1024; idx += 256) {
        const int nn = idx >> 10;
        const int e4 = idx & 1023;
        const float4 v = reinterpret_cast<const float4*>(y + (size_t)(nn * CMID + ch) * 4096)[e4];
        sum += v.x + v.y + v.z + v.w;
        sq  += v.x * v.x + v.y * v.y + v.z * v.z + v.w * v.w;
    }
    __shared__ float rs[256], rq[256];
    rs[tid] = sum; rq[tid] = sq;
    __syncthreads();
    for (int off = 128; off > 0; off >>= 1) {
        if (tid < off) { rs[tid] += rs[tid + off]; rq[tid] += rq[tid + off]; }
        __syncthreads();
    }
    if (tid == 0) {
        const float inv = 1.0f / (float)(BATCH * HOUT * WOUT);
        const float mean = rs[0] * inv;
        const float var  = rq[0] * inv - mean * mean;
        const float a = gamma[ch] * rsqrtf(var + 1e-5f);
        A[ch] = a;
        S[ch] = beta[ch] - mean * a;
    }
}

// ---------------------------------------------------------------------------
// Final merge: out = relu( BN2(O1) + BN12(Y2) )
// ---------------------------------------------------------------------------
__global__ void final_kernel(float* __restrict__ out)
{
    const int idx = blockIdx.x * blockDim.x + threadIdx.x;
    if (idx >= NOUT / 4) return;
    const int c = (idx >> 10) & (CMID - 1);
    const float a2 = g_a2[c], s2 = g_s2[c];
    const float a3 = g_a3[c], s3 = g_s3[c];
    const float4 o = reinterpret_cast<const float4*>(g_O1)[idx];
    const float4 y = reinterpret_cast<const float4*>(g_Y2)[idx];
    float4 r;
    r.x = fmaxf(0.0f, fmaf(o.x, a3, s3) + fmaf(y.x, a2, s2));
    r.y = fmaxf(0.0f, fmaf(o.y, a3, s3) + fmaf(y.y, a2, s2));
    r.z = fmaxf(0.0f, fmaf(o.z, a3, s3) + fmaf(y.z, a2, s2));
    r.w = fmaxf(0.0f, fmaf(o.w, a3, s3) + fmaf(y.w, a2, s2));
    reinterpret_cast<float4*>(out)[idx] = r;
}

// ---------------------------------------------------------------------------
// Launch sequence
// ---------------------------------------------------------------------------
extern "C" void kernel_launch(void* const* d_in, const int* in_sizes, int n_in,
                              void* d_out, int out_size)
{
    const float* x   = (const float*)d_in[0];
    const float* w1  = (const float*)d_in[1];   const float* b1  = (const float*)d_in[2];
    const float* w2  = (const float*)d_in[3];   const float* b2  = (const float*)d_in[4];
    const float* w3  = (const float*)d_in[5];   const float* b3  = (const float*)d_in[6];
    const float* w4  = (const float*)d_in[7];   const float* b4  = (const float*)d_in[8];
    const float* w5  = (const float*)d_in[9];   const float* b5  = (const float*)d_in[10];
    const float* w6  = (const float*)d_in[11];  const float* b6  = (const float*)d_in[12];
    const float* w7  = (const float*)d_in[13];  const float* b7  = (const float*)d_in[14];
    const float* w8  = (const float*)d_in[15];  const float* b8  = (const float*)d_in[16];
    const float* w9  = (const float*)d_in[17];  const float* b9  = (const float*)d_in[18];
    const float* g11 = (const float*)d_in[19];  const float* be11 = (const float*)d_in[20];
    const float* g12 = (const float*)d_in[21];  const float* be12 = (const float*)d_in[22];
    const float* g2  = (const float*)d_in[23];  const float* be2  = (const float*)d_in[24];

    const int SMEM_GEMM = 131072;   // 2 x 64KB double-buffered stages
    cudaFuncSetAttribute(gemm_kernel<512, 32, 4, 2048, false>,
                         cudaFuncAttributeMaxDynamicSharedMemorySize, SMEM_GEMM);
    cudaFuncSetAttribute(gemm_kernel<256, 64, 2, 256, true>,
                         cudaFuncAttributeMaxDynamicSharedMemorySize, SMEM_GEMM);

    // Pre-passes: weights + input transform
    prep_weights_kernel<<<(9 * 2048 * 512) / 256, 256>>>(w1, w2, w3, w4, w5, w6, w7, w8,
                                                         b1, b2, b3, b4, b5, b6, b7, b8);
    prep_w9_kernel<<<(9 * 256 * 256) / 256, 256>>>(w9);
    pad_transpose_kernel<512, 32, false><<<BATCH * 34 * 8, 256>>>(x);

    // Phase-1 GEMM: all 8 unpool convs (M=2048, N=16 imgs x 1024 px)
    gemm_kernel<512, 32, 4, 2048, false><<<dim3(16, 128), 256, SMEM_GEMM>>>(nullptr);

    bn_stats_kernel<<<CMID, 256>>>(0, g11, be11);   // BN11 (folded into phase-2 input)
    bn_stats_kernel<<<CMID, 256>>>(1, g12, be12);   // BN12 (folded into final)

    // relu(BN11(Y1)) -> padded transposed bf16 hi/lo
    pad_transpose_kernel<256, 64, true><<<BATCH * 66 * 4, 256>>>(nullptr);

    // Phase-2 GEMM: conv9 (M=256, N=16 imgs x 4096 px)
    gemm_kernel<256, 64, 2, 256, true><<<dim3(2, 512), 256, SMEM_GEMM>>>(b9);

    bn_stats_kernel<<<CMID, 256>>>(2, g2, be2);     // BN2 (folded into final)
    final_kernel<<<(NOUT / 4 + 255) / 256, 256>>>((float*)d_out);
}

// round 7
// speedup vs baseline: 4.1991x; 1.3265x over previous
#include <cuda_runtime.h>
#include <cuda_fp16.h>
#include <cstdint>

// ---------------------------------------------------------------------------
// Problem constants
// ---------------------------------------------------------------------------
#define BATCH 16
#define CIN   512
#define CMID  256
#define HOUT  64
#define WOUT  64
#define NOUT  (BATCH * CMID * HOUT * WOUT)   // 16,777,216

// ---------------------------------------------------------------------------
// Device-global scratch (no allocations allowed)
// ---------------------------------------------------------------------------
__device__ float g_Y1[NOUT];                 // branch-1 interleaved output (pre-BN)
__device__ float g_Y2[NOUT];                 // branch-2 interleaved output
__device__ float g_O1[NOUT];                 // conv9 output (pre-BN)
__device__ float g_a1[CMID], g_s1[CMID];
__device__ float g_a2[CMID], g_s2[CMID];
__device__ float g_a3[CMID], g_s3[CMID];
__device__ float g_biasAll[2048];

// Padded, channel-innermost activations (single fp16)
__device__ __half g_Xp [BATCH * 34 * 34 * CIN];
__device__ __half g_X2p[BATCH * 66 * 66 * CMID];

// Tap-major weights, fp16 hi/lo split: [tap][M][Cin] (zero-padded to 3x3)
__device__ __half g_Wb_hi[9 * 2048 * CIN];
__device__ __half g_Wb_lo[9 * 2048 * CIN];
__device__ __half g_W9_hi[9 * 256 * CMID];
__device__ __half g_W9_lo[9 * 256 * CMID];

// ---------------------------------------------------------------------------
// Helpers (base sm_80+ features only — valid on plain sm_103 target)
// ---------------------------------------------------------------------------
__device__ __forceinline__ uint32_t smem_u32(const void* p) {
    uint32_t a;
    asm("{ .reg .u64 t; cvta.to.shared.u64 t, %1; cvt.u32.u64 %0, t; }" : "=r"(a) : "l"(p));
    return a;
}
__device__ __forceinline__ uint32_t sw128(uint32_t off) { return off ^ ((off >> 3) & 0x70); }

#define CP16(saddr, gptr) \
    asm volatile("cp.async.cg.shared.global [%0], [%1], 16;" :: "r"(saddr), "l"(gptr))
#define CP_COMMIT() asm volatile("cp.async.commit_group;" ::: "memory")
#define CP_WAIT1()  asm volatile("cp.async.wait_group 1;" ::: "memory")

#define LDSM4(r0, r1, r2, r3, addr) \
    asm volatile("ldmatrix.sync.aligned.m8n8.x4.shared.b16 {%0,%1,%2,%3}, [%4];" \
                 : "=r"(r0), "=r"(r1), "=r"(r2), "=r"(r3) : "r"(addr))

#define MMA_F16(d, a, b) \
    asm volatile("mma.sync.aligned.m16n8k16.row.col.f32.f16.f16.f32 " \
                 "{%0,%1,%2,%3}, {%4,%5,%6,%7}, {%8,%9}, {%0,%1,%2,%3};" \
                 : "+f"((d)[0]), "+f"((d)[1]), "+f"((d)[2]), "+f"((d)[3]) \
                 : "r"((a)[0]), "r"((a)[1]), "r"((a)[2]), "r"((a)[3]),   \
                   "r"((b)[0]), "r"((b)[1]))

// ---------------------------------------------------------------------------
// Pre-pass: pad + transpose to channel-innermost + fp16 convert.
// AFFINE=false: src = x (fp32 NCHW) -> g_Xp.  AFFINE=true: src = g_Y1 with
// relu(BN11) folded -> g_X2p.  Border cells written as zeros.
// ---------------------------------------------------------------------------
template <int C, int H, bool AFFINE>
__global__ void pad_transpose_kernel(const float* __restrict__ src_arg)
{
    constexpr int HP = H + 2, WP = H + 2;
    constexpr int CB = C / 64;
    __shared__ float sm[64][H + 1];

    const int bid = blockIdx.x;
    const int cb  = bid % CB;
    const int y   = (bid / CB) % HP;
    const int img = bid / (CB * HP);
    const int tid = threadIdx.x;

    const float* src = AFFINE ? (const float*)g_Y1 : src_arg;
    __half* oh = (AFFINE ? g_X2p : g_Xp) + ((size_t)(img * HP + y)) * WP * C + cb * 64;

    if (y == 0 || y == HP - 1) {
        for (int t = tid; t < WP * 64; t += 256) {
            int x = t >> 6, ci = t & 63;
            oh[(size_t)x * C + ci] = __float2half_rn(0.0f);
        }
        return;
    }

    for (int t = tid; t < 64 * H; t += 256) {
        int ci = t / H, x = t % H;
        int ch = cb * 64 + ci;
        float v = src[((size_t)(img * C + ch) * H + (y - 1)) * H + x];
        if (AFFINE) v = fmaxf(0.0f, fmaf(v, g_a1[ch], g_s1[ch]));
        sm[ci][x] = v;
    }
    __syncthreads();

    for (int t = tid; t < WP * 64; t += 256) {
        int x = t >> 6, ci = t & 63;
        float v = (x >= 1 && x <= H) ? sm[ci][x - 1] : 0.0f;
        oh[(size_t)x * C + ci] = __float2half_rn(v);
    }
}

// ---------------------------------------------------------------------------
// Pre-pass: 8 conv weight tensors -> tap-major zero-padded-3x3 fp16 hi/lo,
// plus flattened bias table.  Weights exact to ~2^-21 via hi/lo split.
// ---------------------------------------------------------------------------
__global__ void prep_weights_kernel(
    const float* __restrict__ w0, const float* __restrict__ w1,
    const float* __restrict__ w2, const float* __restrict__ w3,
    const float* __restrict__ w4, const float* __restrict__ w5,
    const float* __restrict__ w6, const float* __restrict__ w7,
    const float* __restrict__ b0, const float* __restrict__ b1,
    const float* __restrict__ b2, const float* __restrict__ b3,
    const float* __restrict__ b4, const float* __restrict__ b5,
    const float* __restrict__ b6, const float* __restrict__ b7)
{
    const int idx = blockIdx.x * 256 + threadIdx.x;   // 9*2048*512 elements
    const float* W[8] = {w0, w1, w2, w3, w4, w5, w6, w7};
    const float* B[8] = {b0, b1, b2, b3, b4, b5, b6, b7};
    const int KH[8] = {3, 2, 3, 2, 3, 2, 3, 2};
    const int KW[8] = {3, 3, 2, 2, 3, 3, 2, 2};

    if (idx < 2048) g_biasAll[idx] = B[idx >> 8][idx & 255];
    if (idx >= 9 * 2048 * 512) return;

    const int ci  = idx & 511;
    const int m   = (idx >> 9) & 2047;
    const int tap = idx >> 20;
    const int conv = m >> 8, co = m & 255;
    const int kh = tap / 3, kw = tap % 3;

    float v = 0.0f;
    if (kh < KH[conv] && kw < KW[conv])
        v = W[conv][((size_t)(co * CIN + ci) * KH[conv] + kh) * KW[conv] + kw];

    __half h = __float2half_rn(v);
    g_Wb_hi[idx] = h;
    g_Wb_lo[idx] = __float2half_rn(v - __half2float(h));
}

__global__ void prep_w9_kernel(const float* __restrict__ w9)
{
    const int idx = blockIdx.x * 256 + threadIdx.x;   // 9*256*256
    if (idx >= 9 * 256 * 256) return;
    const int ci = idx & 255;
    const int co = (idx >> 8) & 255;
    const int tap = idx >> 16;
    const int kh = tap / 3, kw = tap % 3;
    float v = w9[((size_t)(co * CMID + ci) * 3 + kh) * 3 + kw];
    __half h = __float2half_rn(v);
    g_W9_hi[idx] = h;
    g_W9_lo[idx] = __float2half_rn(v - __half2float(h));
}

// ---------------------------------------------------------------------------
// mma.sync implicit-conv GEMM, fp16 (A split hi/lo, B single), fp32 accum.
// CTA tile 128(M) x 128(N pixels), warp tile 64x32, K chunked by 64 channels
// at a fixed tap (9*CIN_T/64 chunks), cp.async 3-stage pipeline, 1 sync/chunk.
// PHASE2=false: A=g_Wb (M=2048), B=g_Xp, epilogue interleaves into Y1/Y2.
// PHASE2=true : A=g_W9 (M=256),  B=g_X2p, epilogue -> g_O1 (+b9).
// ---------------------------------------------------------------------------
template <int CIN_T, int WDIM, int ROWS, int MTOT, bool PHASE2>
__global__ __launch_bounds__(256, 1)
void gemm_kernel(const float* __restrict__ bias9)
{
    constexpr int HP = WDIM + 2, WP = WDIM + 2;
    constexpr int NT_PER_IMG = (WDIM * WDIM) / 128;
    constexpr int KCH = CIN_T / 64;
    constexpr int NCHUNK = 9 * KCH;
    constexpr int CI_SHIFT = (WDIM == 32) ? 5 : 6;
    // per-stage smem: AH(16K) AL(16K) B(16K) = 48KB; 3 stages.
    constexpr uint32_t BUF = 49152;

    extern __shared__ char smem[];
    const uint32_t sb = smem_u32(smem);

    const int tid  = threadIdx.x;
    const int wid  = tid >> 5;
    const int lane = tid & 31;
    const int m0   = blockIdx.x * 128;
    const int img  = blockIdx.y / NT_PER_IMG;
    const int i0   = (blockIdx.y % NT_PER_IMG) * ROWS;

    const float4* A4h = reinterpret_cast<const float4*>(PHASE2 ? g_W9_hi : g_Wb_hi);
    const float4* A4l = reinterpret_cast<const float4*>(PHASE2 ? g_W9_lo : g_Wb_lo);
    const float4* B4  = reinterpret_cast<const float4*>(PHASE2 ? g_X2p : g_Xp);

    // ---- staging: 12 cp.async x 16B per thread per chunk ----
    auto stage = [&](int chunk, int buf) {
        const int tap = chunk / KCH;
        const int ci0 = (chunk - tap * KCH) * 64;
        const int kh = tap / 3, kw = tap - kh * 3;
        const uint32_t bb = sb + buf * BUF;
#pragma unroll
        for (int it = 0; it < 4; ++it) {
            const int t = tid + it * 256;
            const int row = t >> 3, g = t & 7;
            const uint32_t off = sw128(row * 128 + g * 16);
            const long srcA = ((((long)(tap * MTOT + m0 + row) * CIN_T + ci0)) >> 3) + g;
            CP16(bb + off,         A4h + srcA);
            CP16(bb + 16384 + off, A4l + srcA);
            const int r = row >> CI_SHIFT, j = row & (WDIM - 1);
            const int y = i0 + r + kh, x = j + kw;
            const long srcB = ((((long)((img * HP + y) * WP + x) * CIN_T + ci0)) >> 3) + g;
            CP16(bb + 32768 + off, B4 + srcB);
        }
    };

    // ---- per-lane ldmatrix addressing components ----
    const int sub = lane >> 3, r8 = lane & 7;
    const int wm = wid & 1, wn = wid >> 1;
    const int arow_b = wm * 64 + ((sub & 1) << 3) + r8;   // + mt*16
    const int akoff  = (sub >> 1) << 4;
    const int brow_b = wn * 32 + ((sub >> 1) << 3) + r8;  // + q*16
    const int bkoff  = (sub & 1) << 4;

    float acc[4][4][4];
#pragma unroll
    for (int a = 0; a < 4; ++a)
#pragma unroll
        for (int b = 0; b < 4; ++b)
#pragma unroll
            for (int c = 0; c < 4; ++c) acc[a][b][c] = 0.0f;

    auto compute = [&](int buf) {
        const uint32_t AH = sb + buf * BUF;
        const uint32_t AL = AH + 16384, BB = AH + 32768;
#pragma unroll
        for (int kk = 0; kk < 4; ++kk) {
            uint32_t ah[4][4], al[4][4], bf[4][2];
            // B fragments (4 n8 tiles via 2 x4 loads) — shared by both products
#pragma unroll
            for (int q = 0; q < 2; ++q) {
                const uint32_t ad = BB + sw128((brow_b + q * 16) * 128 + kk * 32 + bkoff);
                LDSM4(bf[2 * q][0], bf[2 * q][1], bf[2 * q + 1][0], bf[2 * q + 1][1], ad);
            }
            // A_hi fragments + hh product
#pragma unroll
            for (int mt = 0; mt < 4; ++mt) {
                const uint32_t ad = AH + sw128((arow_b + mt * 16) * 128 + kk * 32 + akoff);
                LDSM4(ah[mt][0], ah[mt][1], ah[mt][2], ah[mt][3], ad);
            }
#pragma unroll
            for (int mt = 0; mt < 4; ++mt)
#pragma unroll
                for (int nt = 0; nt < 4; ++nt)
                    MMA_F16(acc[mt][nt], ah[mt], bf[nt]);
            // A_lo fragments + lh product
#pragma unroll
            for (int mt = 0; mt < 4; ++mt) {
                const uint32_t ad = AL + sw128((arow_b + mt * 16) * 128 + kk * 32 + akoff);
                LDSM4(al[mt][0], al[mt][1], al[mt][2], al[mt][3], ad);
            }
#pragma unroll
            for (int mt = 0; mt < 4; ++mt)
#pragma unroll
                for (int nt = 0; nt < 4; ++nt)
                    MMA_F16(acc[mt][nt], al[mt], bf[nt]);
        }
    };

    // ---- 3-stage pipeline, one __syncthreads per chunk ----
    stage(0, 0); CP_COMMIT();
    stage(1, 1); CP_COMMIT();
    for (int c = 0; c < NCHUNK; ++c) {
        CP_WAIT1();            // chunk c landed
        __syncthreads();       // all warps done with compute(c-1); data visible
        if (c + 2 < NCHUNK) stage(c + 2, (c + 2) % 3);
        CP_COMMIT();
        compute(c % 3);
    }

    // ---- epilogue: scatter fragments to gmem with folded interleave ----
    const float* bias = PHASE2 ? bias9 : g_biasAll;
    int qr = 0, qc = 0, coBase = m0;
    float* Ybuf = g_O1;
    if (!PHASE2) {
        const int conv = m0 >> 8;
        const int quad = conv & 3;
        qr = quad & 1;
        qc = (quad >> 1) & 1;
        coBase = m0 & 255;
        Ybuf = (conv >= 4) ? g_Y2 : g_Y1;
    }

#pragma unroll
    for (int mt = 0; mt < 4; ++mt) {
        const int rowA = wm * 64 + mt * 16 + (lane >> 2);
        const float bv0 = bias[m0 + rowA];
        const float bv8 = bias[m0 + rowA + 8];
        const int co0 = coBase + rowA;
#pragma unroll
        for (int nt = 0; nt < 4; ++nt) {
            const int p = wn * 32 + nt * 8 + 2 * (lane & 3);
            int yy, xx, xstep;
            if (!PHASE2) {
                const int pr = p >> 5, pc = p & 31;
                yy = 2 * (i0 + pr) + qr;
                xx = 2 * pc + qc;
                xstep = 2;
            } else {
                const int pr = p >> 6, pc = p & 63;
                yy = i0 + pr;
                xx = pc;
                xstep = 1;
            }
            float* base0 = Ybuf + ((size_t)(img * CMID + co0) * HOUT + yy) * WOUT + xx;
            float* base8 = base0 + (size_t)8 * HOUT * WOUT;
            base0[0]     = acc[mt][nt][0] + bv0;
            base0[xstep] = acc[mt][nt][1] + bv0;
            base8[0]     = acc[mt][nt][2] + bv8;
            base8[xstep] = acc[mt][nt][3] + bv8;
        }
    }
}

// ---------------------------------------------------------------------------
// BN batch stats (biased, over N,H,W) -> folded affine (a, s).
// ---------------------------------------------------------------------------
__global__ void bn_stats_kernel(int which,
                                const float* __restrict__ gamma,
                                const float* __restrict__ beta)
{
    const int ch  = blockIdx.x;
    const int tid = threadIdx.x;
    const float* y = (which == 0) ? g_Y1 : (which == 1) ? g_Y2 : g_O1;
    float* A = (which == 0) ? g_a1 : (which == 1) ? g_a2 : g_a3;
    float* S = (which == 0) ? g_s1 : (which == 1) ? g_s2 : g_s3;

    float sum = 0.0f, sq = 0.0f;
    for (int idx = tid; idx < BATCH * 1024; idx += 256) {
        const int nn = idx >> 10;
        const int e4 = idx & 1023;
        const float4 v = reinterpret_cast<const float4*>(y + (size_t)(nn * CMID + ch) * 4096)[e4];
        sum += v.x + v.y + v.z + v.w;
        sq  += v.x * v.x + v.y * v.y + v.z * v.z + v.w * v.w;
    }
    __shared__ float rs[256], rq[256];
    rs[tid] = sum; rq[tid] = sq;
    __syncthreads();
    for (int off = 128; off > 0; off >>= 1) {
        if (tid < off) { rs[tid] += rs[tid + off]; rq[tid] += rq[tid + off]; }
        __syncthreads();
    }
    if (tid == 0) {
        const float inv = 1.0f / (float)(BATCH * HOUT * WOUT);
        const float mean = rs[0] * inv;
        const float var  = rq[0] * inv - mean * mean;
        const float a = gamma[ch] * rsqrtf(var + 1e-5f);
        A[ch] = a;
        S[ch] = beta[ch] - mean * a;
    }
}

// ---------------------------------------------------------------------------
// Final merge: out = relu( BN2(O1) + BN12(Y2) )
// ---------------------------------------------------------------------------
__global__ void final_kernel(float* __restrict__ out)
{
    const int idx = blockIdx.x * blockDim.x + threadIdx.x;
    if (idx >= NOUT / 4) return;
    const int c = (idx >> 10) & (CMID - 1);
    const float a2 = g_a2[c], s2 = g_s2[c];
    const float a3 = g_a3[c], s3 = g_s3[c];
    const float4 o = reinterpret_cast<const float4*>(g_O1)[idx];
    const float4 y = reinterpret_cast<const float4*>(g_Y2)[idx];
    float4 r;
    r.x = fmaxf(0.0f, fmaf(o.x, a3, s3) + fmaf(y.x, a2, s2));
    r.y = fmaxf(0.0f, fmaf(o.y, a3, s3) + fmaf(y.y, a2, s2));
    r.z = fmaxf(0.0f, fmaf(o.z, a3, s3) + fmaf(y.z, a2, s2));
    r.w = fmaxf(0.0f, fmaf(o.w, a3, s3) + fmaf(y.w, a2, s2));
    reinterpret_cast<float4*>(out)[idx] = r;
}

// ---------------------------------------------------------------------------
// Launch sequence
// ---------------------------------------------------------------------------
extern "C" void kernel_launch(void* const* d_in, const int* in_sizes, int n_in,
                              void* d_out, int out_size)
{
    const float* x   = (const float*)d_in[0];
    const float* w1  = (const float*)d_in[1];   const float* b1  = (const float*)d_in[2];
    const float* w2  = (const float*)d_in[3];   const float* b2  = (const float*)d_in[4];
    const float* w3  = (const float*)d_in[5];   const float* b3  = (const float*)d_in[6];
    const float* w4  = (const float*)d_in[7];   const float* b4  = (const float*)d_in[8];
    const float* w5  = (const float*)d_in[9];   const float* b5  = (const float*)d_in[10];
    const float* w6  = (const float*)d_in[11];  const float* b6  = (const float*)d_in[12];
    const float* w7  = (const float*)d_in[13];  const float* b7  = (const float*)d_in[14];
    const float* w8  = (const float*)d_in[15];  const float* b8  = (const float*)d_in[16];
    const float* w9  = (const float*)d_in[17];  const float* b9  = (const float*)d_in[18];
    const float* g11 = (const float*)d_in[19];  const float* be11 = (const float*)d_in[20];
    const float* g12 = (const float*)d_in[21];  const float* be12 = (const float*)d_in[22];
    const float* g2  = (const float*)d_in[23];  const float* be2  = (const float*)d_in[24];

    const int SMEM_GEMM = 3 * 49152;   // 147,456 B (3-stage pipeline)
    cudaFuncSetAttribute(gemm_kernel<512, 32, 4, 2048, false>,
                         cudaFuncAttributeMaxDynamicSharedMemorySize, SMEM_GEMM);
    cudaFuncSetAttribute(gemm_kernel<256, 64, 2, 256, true>,
                         cudaFuncAttributeMaxDynamicSharedMemorySize, SMEM_GEMM);

    // Pre-passes: weights + input transform
    prep_weights_kernel<<<(9 * 2048 * 512) / 256, 256>>>(w1, w2, w3, w4, w5, w6, w7, w8,
                                                         b1, b2, b3, b4, b5, b6, b7, b8);
    prep_w9_kernel<<<(9 * 256 * 256) / 256, 256>>>(w9);
    pad_transpose_kernel<512, 32, false><<<BATCH * 34 * 8, 256>>>(x);

    // Phase-1 GEMM: all 8 unpool convs (M=2048, N=16 imgs x 1024 px)
    gemm_kernel<512, 32, 4, 2048, false><<<dim3(16, 128), 256, SMEM_GEMM>>>(nullptr);

    bn_stats_kernel<<<CMID, 256>>>(0, g11, be11);   // BN11 (folded into phase-2 input)
    bn_stats_kernel<<<CMID, 256>>>(1, g12, be12);   // BN12 (folded into final)

    // relu(BN11(Y1)) -> padded transposed fp16
    pad_transpose_kernel<256, 64, true><<<BATCH * 66 * 4, 256>>>(nullptr);

    // Phase-2 GEMM: conv9 (M=256, N=16 imgs x 4096 px)
    gemm_kernel<256, 64, 2, 256, true><<<dim3(2, 512), 256, SMEM_GEMM>>>(b9);

    bn_stats_kernel<<<CMID, 256>>>(2, g2, be2);     // BN2 (folded into final)
    final_kernel<<<(NOUT / 4 + 255) / 256, 256>>>((float*)d_out);
}

// round 8
// speedup vs baseline: 7.2493x; 1.7264x over previous
#include <cuda_runtime.h>
#include <cuda_fp16.h>
#include <cstdint>

// ---------------------------------------------------------------------------
// Problem constants
// ---------------------------------------------------------------------------
#define BATCH 16
#define CIN   512
#define CMID  256
#define HOUT  64
#define WOUT  64
#define NOUT  (BATCH * CMID * HOUT * WOUT)   // 16,777,216

// ---------------------------------------------------------------------------
// Device-global scratch (no allocations allowed)
// ---------------------------------------------------------------------------
__device__ float g_Y1[NOUT];                 // branch-1 interleaved output (pre-BN)
__device__ float g_Y2[NOUT];                 // branch-2 interleaved output
__device__ float g_O1[NOUT];                 // conv9 output (pre-BN)
__device__ float g_a1[CMID], g_s1[CMID];
__device__ float g_a2[CMID], g_s2[CMID];
__device__ float g_a3[CMID], g_s3[CMID];
__device__ float g_biasAll[2048];

// Padded, channel-innermost activations (fp16)
__device__ __half g_Xp [BATCH * 34 * 34 * CIN];
__device__ __half g_X2p[BATCH * 66 * 66 * CMID];

// Tap-major weights (fp16, zero-padded to 3x3): [tap][M][Cin]
__device__ __half g_Wb[9 * 2048 * CIN];
__device__ __half g_W9[9 * 256 * CMID];

// ---------------------------------------------------------------------------
// Helpers (base sm_80+ features only — valid on plain sm_103 target)
// ---------------------------------------------------------------------------
__device__ __forceinline__ uint32_t smem_u32(const void* p) {
    uint32_t a;
    asm("{ .reg .u64 t; cvta.to.shared.u64 t, %1; cvt.u32.u64 %0, t; }" : "=r"(a) : "l"(p));
    return a;
}
__device__ __forceinline__ uint32_t sw128(uint32_t off) { return off ^ ((off >> 3) & 0x70); }

#define CP16(saddr, gptr) \
    asm volatile("cp.async.cg.shared.global [%0], [%1], 16;" :: "r"(saddr), "l"(gptr))
#define CP_COMMIT() asm volatile("cp.async.commit_group;" ::: "memory")
#define CP_WAIT1()  asm volatile("cp.async.wait_group 1;" ::: "memory")

#define LDSM4(r0, r1, r2, r3, addr) \
    asm volatile("ldmatrix.sync.aligned.m8n8.x4.shared.b16 {%0,%1,%2,%3}, [%4];" \
                 : "=r"(r0), "=r"(r1), "=r"(r2), "=r"(r3) : "r"(addr))

#define MMA_F16(d, a, b) \
    asm volatile("mma.sync.aligned.m16n8k16.row.col.f32.f16.f16.f32 " \
                 "{%0,%1,%2,%3}, {%4,%5,%6,%7}, {%8,%9}, {%0,%1,%2,%3};" \
                 : "+f"((d)[0]), "+f"((d)[1]), "+f"((d)[2]), "+f"((d)[3]) \
                 : "r"((a)[0]), "r"((a)[1]), "r"((a)[2]), "r"((a)[3]),   \
                   "r"((b)[0]), "r"((b)[1]))

// ---------------------------------------------------------------------------
// Pre-pass: pad + transpose to channel-innermost + fp16 convert.
// AFFINE=false: src = x (fp32 NCHW) -> g_Xp.  AFFINE=true: src = g_Y1 with
// relu(BN11) folded -> g_X2p.  Border cells written as zeros.
// ---------------------------------------------------------------------------
template <int C, int H, bool AFFINE>
__global__ void pad_transpose_kernel(const float* __restrict__ src_arg)
{
    constexpr int HP = H + 2, WP = H + 2;
    constexpr int CB = C / 64;
    __shared__ float sm[64][H + 1];

    const int bid = blockIdx.x;
    const int cb  = bid % CB;
    const int y   = (bid / CB) % HP;
    const int img = bid / (CB * HP);
    const int tid = threadIdx.x;

    const float* src = AFFINE ? (const float*)g_Y1 : src_arg;
    __half* oh = (AFFINE ? g_X2p : g_Xp) + ((size_t)(img * HP + y)) * WP * C + cb * 64;

    if (y == 0 || y == HP - 1) {
        for (int t = tid; t < WP * 64; t += 256) {
            int x = t >> 6, ci = t & 63;
            oh[(size_t)x * C + ci] = __float2half_rn(0.0f);
        }
        return;
    }

    for (int t = tid; t < 64 * H; t += 256) {
        int ci = t / H, x = t % H;
        int ch = cb * 64 + ci;
        float v = src[((size_t)(img * C + ch) * H + (y - 1)) * H + x];
        if (AFFINE) v = fmaxf(0.0f, fmaf(v, g_a1[ch], g_s1[ch]));
        sm[ci][x] = v;
    }
    __syncthreads();

    for (int t = tid; t < WP * 64; t += 256) {
        int x = t >> 6, ci = t & 63;
        float v = (x >= 1 && x <= H) ? sm[ci][x - 1] : 0.0f;
        oh[(size_t)x * C + ci] = __float2half_rn(v);
    }
}

// ---------------------------------------------------------------------------
// Pre-pass: 8 conv weight tensors -> tap-major zero-padded-3x3 fp16,
// plus flattened bias table.
// ---------------------------------------------------------------------------
__global__ void prep_weights_kernel(
    const float* __restrict__ w0, const float* __restrict__ w1,
    const float* __restrict__ w2, const float* __restrict__ w3,
    const float* __restrict__ w4, const float* __restrict__ w5,
    const float* __restrict__ w6, const float* __restrict__ w7,
    const float* __restrict__ b0, const float* __restrict__ b1,
    const float* __restrict__ b2, const float* __restrict__ b3,
    const float* __restrict__ b4, const float* __restrict__ b5,
    const float* __restrict__ b6, const float* __restrict__ b7)
{
    const int idx = blockIdx.x * 256 + threadIdx.x;   // 9*2048*512 elements
    const float* W[8] = {w0, w1, w2, w3, w4, w5, w6, w7};
    const float* B[8] = {b0, b1, b2, b3, b4, b5, b6, b7};
    const int KH[8] = {3, 2, 3, 2, 3, 2, 3, 2};
    const int KW[8] = {3, 3, 2, 2, 3, 3, 2, 2};

    if (idx < 2048) g_biasAll[idx] = B[idx >> 8][idx & 255];
    if (idx >= 9 * 2048 * 512) return;

    const int ci  = idx & 511;
    const int m   = (idx >> 9) & 2047;
    const int tap = idx >> 20;
    const int conv = m >> 8, co = m & 255;
    const int kh = tap / 3, kw = tap % 3;

    float v = 0.0f;
    if (kh < KH[conv] && kw < KW[conv])
        v = W[conv][((size_t)(co * CIN + ci) * KH[conv] + kh) * KW[conv] + kw];

    g_Wb[idx] = __float2half_rn(v);
}

__global__ void prep_w9_kernel(const float* __restrict__ w9)
{
    const int idx = blockIdx.x * 256 + threadIdx.x;   // 9*256*256
    if (idx >= 9 * 256 * 256) return;
    const int ci = idx & 255;
    const int co = (idx >> 8) & 255;
    const int tap = idx >> 16;
    const int kh = tap / 3, kw = tap % 3;
    float v = w9[((size_t)(co * CMID + ci) * 3 + kh) * 3 + kw];
    g_W9[idx] = __float2half_rn(v);
}

// ---------------------------------------------------------------------------
// mma.sync implicit-conv GEMM, fp16 x fp16 -> fp32 accum.
// CTA tile 128(M) x 128(N pixels), warp tile 64x32, K chunked by 64 channels
// at a fixed tap (9*CIN_T/64 chunks), cp.async 3-stage pipeline, 2 CTAs/SM.
// PHASE2=false: A=g_Wb (M=2048), B=g_Xp, epilogue interleaves into Y1/Y2.
// PHASE2=true : A=g_W9 (M=256),  B=g_X2p, epilogue -> g_O1 (+b9).
// ---------------------------------------------------------------------------
template <int CIN_T, int WDIM, int ROWS, int MTOT, bool PHASE2>
__global__ __launch_bounds__(256, 2)
void gemm_kernel(const float* __restrict__ bias9)
{
    constexpr int HP = WDIM + 2, WP = WDIM + 2;
    constexpr int NT_PER_IMG = (WDIM * WDIM) / 128;
    constexpr int KCH = CIN_T / 64;
    constexpr int NCHUNK = 9 * KCH;
    constexpr int CI_SHIFT = (WDIM == 32) ? 5 : 6;
    // per-stage smem: A(16K) + B(16K) = 32KB; 3 stages = 96KB; 2 CTAs/SM.
    constexpr uint32_t BUF = 32768;

    extern __shared__ char smem[];
    const uint32_t sb = smem_u32(smem);

    const int tid  = threadIdx.x;
    const int wid  = tid >> 5;
    const int lane = tid & 31;
    const int m0   = blockIdx.x * 128;
    const int img  = blockIdx.y / NT_PER_IMG;
    const int i0   = (blockIdx.y % NT_PER_IMG) * ROWS;

    const float4* A4 = reinterpret_cast<const float4*>(PHASE2 ? g_W9 : g_Wb);
    const float4* B4 = reinterpret_cast<const float4*>(PHASE2 ? g_X2p : g_Xp);

    // ---- staging: 8 cp.async x 16B per thread per chunk ----
    auto stage = [&](int chunk, int buf) {
        const int tap = chunk / KCH;
        const int ci0 = (chunk - tap * KCH) * 64;
        const int kh = tap / 3, kw = tap - kh * 3;
        const uint32_t bb = sb + buf * BUF;
#pragma unroll
        for (int it = 0; it < 4; ++it) {
            const int t = tid + it * 256;
            const int row = t >> 3, g = t & 7;
            const uint32_t off = sw128(row * 128 + g * 16);
            const long srcA = ((((long)(tap * MTOT + m0 + row) * CIN_T + ci0)) >> 3) + g;
            CP16(bb + off, A4 + srcA);
            const int r = row >> CI_SHIFT, j = row & (WDIM - 1);
            const int y = i0 + r + kh, x = j + kw;
            const long srcB = ((((long)((img * HP + y) * WP + x) * CIN_T + ci0)) >> 3) + g;
            CP16(bb + 16384 + off, B4 + srcB);
        }
    };

    // ---- per-lane ldmatrix addressing components ----
    const int sub = lane >> 3, r8 = lane & 7;
    const int wm = wid & 1, wn = wid >> 1;
    const int arow_b = wm * 64 + ((sub & 1) << 3) + r8;   // + mt*16
    const int akoff  = (sub >> 1) << 4;
    const int brow_b = wn * 32 + ((sub >> 1) << 3) + r8;  // + q*16
    const int bkoff  = (sub & 1) << 4;

    float acc[4][4][4];
#pragma unroll
    for (int a = 0; a < 4; ++a)
#pragma unroll
        for (int b = 0; b < 4; ++b)
#pragma unroll
            for (int c = 0; c < 4; ++c) acc[a][b][c] = 0.0f;

    auto compute = [&](int buf) {
        const uint32_t AB = sb + buf * BUF;
        const uint32_t BB = AB + 16384;
#pragma unroll
        for (int kk = 0; kk < 4; ++kk) {
            uint32_t af[4][4], bf[4][2];
#pragma unroll
            for (int q = 0; q < 2; ++q) {
                const uint32_t ad = BB + sw128((brow_b + q * 16) * 128 + kk * 32 + bkoff);
                LDSM4(bf[2 * q][0], bf[2 * q][1], bf[2 * q + 1][0], bf[2 * q + 1][1], ad);
            }
#pragma unroll
            for (int mt = 0; mt < 4; ++mt) {
                const uint32_t ad = AB + sw128((arow_b + mt * 16) * 128 + kk * 32 + akoff);
                LDSM4(af[mt][0], af[mt][1], af[mt][2], af[mt][3], ad);
            }
#pragma unroll
            for (int mt = 0; mt < 4; ++mt)
#pragma unroll
                for (int nt = 0; nt < 4; ++nt)
                    MMA_F16(acc[mt][nt], af[mt], bf[nt]);
        }
    };

    // ---- 3-stage pipeline, one __syncthreads per chunk ----
    stage(0, 0); CP_COMMIT();
    stage(1, 1); CP_COMMIT();
    for (int c = 0; c < NCHUNK; ++c) {
        CP_WAIT1();            // chunk c landed
        __syncthreads();       // all warps done with compute(c-1); data visible
        if (c + 2 < NCHUNK) stage(c + 2, (c + 2) % 3);
        CP_COMMIT();
        compute(c % 3);
    }

    // ---- epilogue: scatter fragments to gmem with folded interleave ----
    const float* bias = PHASE2 ? bias9 : g_biasAll;
    int qr = 0, qc = 0, coBase = m0;
    float* Ybuf = g_O1;
    if (!PHASE2) {
        const int conv = m0 >> 8;
        const int quad = conv & 3;
        qr = quad & 1;
        qc = (quad >> 1) & 1;
        coBase = m0 & 255;
        Ybuf = (conv >= 4) ? g_Y2 : g_Y1;
    }

#pragma unroll
    for (int mt = 0; mt < 4; ++mt) {
        const int rowA = wm * 64 + mt * 16 + (lane >> 2);
        const float bv0 = bias[m0 + rowA];
        const float bv8 = bias[m0 + rowA + 8];
        const int co0 = coBase + rowA;
#pragma unroll
        for (int nt = 0; nt < 4; ++nt) {
            const int p = wn * 32 + nt * 8 + 2 * (lane & 3);
            int yy, xx, xstep;
            if (!PHASE2) {
                const int pr = p >> 5, pc = p & 31;
                yy = 2 * (i0 + pr) + qr;
                xx = 2 * pc + qc;
                xstep = 2;
            } else {
                const int pr = p >> 6, pc = p & 63;
                yy = i0 + pr;
                xx = pc;
                xstep = 1;
            }
            float* base0 = Ybuf + ((size_t)(img * CMID + co0) * HOUT + yy) * WOUT + xx;
            float* base8 = base0 + (size_t)8 * HOUT * WOUT;
            base0[0]     = acc[mt][nt][0] + bv0;
            base0[xstep] = acc[mt][nt][1] + bv0;
            base8[0]     = acc[mt][nt][2] + bv8;
            base8[xstep] = acc[mt][nt][3] + bv8;
        }
    }
}

// ---------------------------------------------------------------------------
// BN batch stats (biased, over N,H,W) -> folded affine (a, s).
// ---------------------------------------------------------------------------
__global__ void bn_stats_kernel(int which,
                                const float* __restrict__ gamma,
                                const float* __restrict__ beta)
{
    const int ch  = blockIdx.x;
    const int tid = threadIdx.x;
    const float* y = (which == 0) ? g_Y1 : (which == 1) ? g_Y2 : g_O1;
    float* A = (which == 0) ? g_a1 : (which == 1) ? g_a2 : g_a3;
    float* S = (which == 0) ? g_s1 : (which == 1) ? g_s2 : g_s3;

    float sum = 0.0f, sq = 0.0f;
    for (int idx = tid; idx < BATCH * 1024; idx += 256) {
        const int nn = idx >> 10;
        const int e4 = idx & 1023;
        const float4 v = reinterpret_cast<const float4*>(y + (size_t)(nn * CMID + ch) * 4096)[e4];
        sum += v.x + v.y + v.z + v.w;
        sq  += v.x * v.x + v.y * v.y + v.z * v.z + v.w * v.w;
    }
    __shared__ float rs[256], rq[256];
    rs[tid] = sum; rq[tid] = sq;
    __syncthreads();
    for (int off = 128; off > 0; off >>= 1) {
        if (tid < off) { rs[tid] += rs[tid + off]; rq[tid] += rq[tid + off]; }
        __syncthreads();
    }
    if (tid == 0) {
        const float inv = 1.0f / (float)(BATCH * HOUT * WOUT);
        const float mean = rs[0] * inv;
        const float var  = rq[0] * inv - mean * mean;
        const float a = gamma[ch] * rsqrtf(var + 1e-5f);
        A[ch] = a;
        S[ch] = beta[ch] - mean * a;
    }
}

// ---------------------------------------------------------------------------
// Final merge: out = relu( BN2(O1) + BN12(Y2) )
// ---------------------------------------------------------------------------
__global__ void final_kernel(float* __restrict__ out)
{
    const int idx = blockIdx.x * blockDim.x + threadIdx.x;
    if (idx >= NOUT / 4) return;
    const int c = (idx >> 10) & (CMID - 1);
    const float a2 = g_a2[c], s2 = g_s2[c];
    const float a3 = g_a3[c], s3 = g_s3[c];
    const float4 o = reinterpret_cast<const float4*>(g_O1)[idx];
    const float4 y = reinterpret_cast<const float4*>(g_Y2)[idx];
    float4 r;
    r.x = fmaxf(0.0f, fmaf(o.x, a3, s3) + fmaf(y.x, a2, s2));
    r.y = fmaxf(0.0f, fmaf(o.y, a3, s3) + fmaf(y.y, a2, s2));
    r.z = fmaxf(0.0f, fmaf(o.z, a3, s3) + fmaf(y.z, a2, s2));
    r.w = fmaxf(0.0f, fmaf(o.w, a3, s3) + fmaf(y.w, a2, s2));
    reinterpret_cast<float4*>(out)[idx] = r;
}

// ---------------------------------------------------------------------------
// Launch sequence
// ---------------------------------------------------------------------------
extern "C" void kernel_launch(void* const* d_in, const int* in_sizes, int n_in,
                              void* d_out, int out_size)
{
    const float* x   = (const float*)d_in[0];
    const float* w1  = (const float*)d_in[1];   const float* b1  = (const float*)d_in[2];
    const float* w2  = (const float*)d_in[3];   const float* b2  = (const float*)d_in[4];
    const float* w3  = (const float*)d_in[5];   const float* b3  = (const float*)d_in[6];
    const float* w4  = (const float*)d_in[7];   const float* b4  = (const float*)d_in[8];
    const float* w5  = (const float*)d_in[9];   const float* b5  = (const float*)d_in[10];
    const float* w6  = (const float*)d_in[11];  const float* b6  = (const float*)d_in[12];
    const float* w7  = (const float*)d_in[13];  const float* b7  = (const float*)d_in[14];
    const float* w8  = (const float*)d_in[15];  const float* b8  = (const float*)d_in[16];
    const float* w9  = (const float*)d_in[17];  const float* b9  = (const float*)d_in[18];
    const float* g11 = (const float*)d_in[19];  const float* be11 = (const float*)d_in[20];
    const float* g12 = (const float*)d_in[21];  const float* be12 = (const float*)d_in[22];
    const float* g2  = (const float*)d_in[23];  const float* be2  = (const float*)d_in[24];

    const int SMEM_GEMM = 3 * 32768;   // 98,304 B (3-stage pipeline, 2 CTAs/SM)
    cudaFuncSetAttribute(gemm_kernel<512, 32, 4, 2048, false>,
                         cudaFuncAttributeMaxDynamicSharedMemorySize, SMEM_GEMM);
    cudaFuncSetAttribute(gemm_kernel<256, 64, 2, 256, true>,
                         cudaFuncAttributeMaxDynamicSharedMemorySize, SMEM_GEMM);

    // Pre-passes: weights + input transform
    prep_weights_kernel<<<(9 * 2048 * 512) / 256, 256>>>(w1, w2, w3, w4, w5, w6, w7, w8,
                                                         b1, b2, b3, b4, b5, b6, b7, b8);
    prep_w9_kernel<<<(9 * 256 * 256) / 256, 256>>>(w9);
    pad_transpose_kernel<512, 32, false><<<BATCH * 34 * 8, 256>>>(x);

    // Phase-1 GEMM: all 8 unpool convs (M=2048, N=16 imgs x 1024 px)
    gemm_kernel<512, 32, 4, 2048, false><<<dim3(16, 128), 256, SMEM_GEMM>>>(nullptr);

    bn_stats_kernel<<<CMID, 256>>>(0, g11, be11);   // BN11 (folded into phase-2 input)
    bn_stats_kernel<<<CMID, 256>>>(1, g12, be12);   // BN12 (folded into final)

    // relu(BN11(Y1)) -> padded transposed fp16
    pad_transpose_kernel<256, 64, true><<<BATCH * 66 * 4, 256>>>(nullptr);

    // Phase-2 GEMM: conv9 (M=256, N=16 imgs x 4096 px)
    gemm_kernel<256, 64, 2, 256, true><<<dim3(2, 512), 256, SMEM_GEMM>>>(b9);

    bn_stats_kernel<<<CMID, 256>>>(2, g2, be2);     // BN2 (folded into final)
    final_kernel<<<(NOUT / 4 + 255) / 256, 256>>>((float*)d_out);
}

// round 9
// speedup vs baseline: 7.7774x; 1.0728x over previous
#include <cuda_runtime.h>
#include <cuda_fp16.h>
#include <cstdint>

// ---------------------------------------------------------------------------
// Problem constants
// ---------------------------------------------------------------------------
#define BATCH 16
#define CIN   512
#define CMID  256
#define HOUT  64
#define WOUT  64
#define NOUT  (BATCH * CMID * HOUT * WOUT)   // 16,777,216

// ---------------------------------------------------------------------------
// Device-global scratch (no allocations allowed)
// ---------------------------------------------------------------------------
__device__ float g_Y1[NOUT];                 // branch-1 interleaved output (pre-BN)
__device__ float g_Y2[NOUT];                 // branch-2 interleaved output
__device__ float g_O1[NOUT];                 // conv9 output (pre-BN)
__device__ float g_a1[CMID], g_s1[CMID];
__device__ float g_a2[CMID], g_s2[CMID];
__device__ float g_a3[CMID], g_s3[CMID];
__device__ float g_biasAll[2048];

// Padded, channel-innermost activations (fp16)
__device__ __half g_Xp [BATCH * 34 * 34 * CIN];
__device__ __half g_X2p[BATCH * 66 * 66 * CMID];

// Tap-major weights (fp16, zero-padded to 3x3): [tap][M][Cin]
__device__ __half g_Wb[9 * 2048 * CIN];
__device__ __half g_W9[9 * 256 * CMID];

// ---------------------------------------------------------------------------
// Helpers (base sm_80+ features only — valid on plain sm_103 target)
// ---------------------------------------------------------------------------
__device__ __forceinline__ uint32_t smem_u32(const void* p) {
    uint32_t a;
    asm("{ .reg .u64 t; cvta.to.shared.u64 t, %1; cvt.u32.u64 %0, t; }" : "=r"(a) : "l"(p));
    return a;
}
__device__ __forceinline__ uint32_t sw128(uint32_t off) { return off ^ ((off >> 3) & 0x70); }

#define CP16(saddr, gptr) \
    asm volatile("cp.async.cg.shared.global [%0], [%1], 16;" :: "r"(saddr), "l"(gptr))
#define CP_COMMIT() asm volatile("cp.async.commit_group;" ::: "memory")
#define CP_WAIT1()  asm volatile("cp.async.wait_group 1;" ::: "memory")

#define LDSM4(r0, r1, r2, r3, addr) \
    asm volatile("ldmatrix.sync.aligned.m8n8.x4.shared.b16 {%0,%1,%2,%3}, [%4];" \
                 : "=r"(r0), "=r"(r1), "=r"(r2), "=r"(r3) : "r"(addr))

#define MMA_F16(d, a, b) \
    asm volatile("mma.sync.aligned.m16n8k16.row.col.f32.f16.f16.f32 " \
                 "{%0,%1,%2,%3}, {%4,%5,%6,%7}, {%8,%9}, {%0,%1,%2,%3};" \
                 : "+f"((d)[0]), "+f"((d)[1]), "+f"((d)[2]), "+f"((d)[3]) \
                 : "r"((a)[0]), "r"((a)[1]), "r"((a)[2]), "r"((a)[3]),   \
                   "r"((b)[0]), "r"((b)[1]))

// ---------------------------------------------------------------------------
// Pre-pass: pad + transpose to channel-innermost + fp16 convert.
// AFFINE=false: src = x (fp32 NCHW) -> g_Xp.  AFFINE=true: src = g_Y1 with
// relu(BN11) folded -> g_X2p.  Border cells written as zeros.
// ---------------------------------------------------------------------------
template <int C, int H, bool AFFINE>
__global__ void pad_transpose_kernel(const float* __restrict__ src_arg)
{
    constexpr int HP = H + 2, WP = H + 2;
    constexpr int CB = C / 64;
    __shared__ float sm[64][H + 1];

    const int bid = blockIdx.x;
    const int cb  = bid % CB;
    const int y   = (bid / CB) % HP;
    const int img = bid / (CB * HP);
    const int tid = threadIdx.x;

    const float* src = AFFINE ? (const float*)g_Y1 : src_arg;
    __half* oh = (AFFINE ? g_X2p : g_Xp) + ((size_t)(img * HP + y)) * WP * C + cb * 64;

    if (y == 0 || y == HP - 1) {
        for (int t = tid; t < WP * 64; t += 256) {
            int x = t >> 6, ci = t & 63;
            oh[(size_t)x * C + ci] = __float2half_rn(0.0f);
        }
        return;
    }

    for (int t = tid; t < 64 * H; t += 256) {
        int ci = t / H, x = t % H;
        int ch = cb * 64 + ci;
        float v = src[((size_t)(img * C + ch) * H + (y - 1)) * H + x];
        if (AFFINE) v = fmaxf(0.0f, fmaf(v, g_a1[ch], g_s1[ch]));
        sm[ci][x] = v;
    }
    __syncthreads();

    for (int t = tid; t < WP * 64; t += 256) {
        int x = t >> 6, ci = t & 63;
        float v = (x >= 1 && x <= H) ? sm[ci][x - 1] : 0.0f;
        oh[(size_t)x * C + ci] = __float2half_rn(v);
    }
}

// ---------------------------------------------------------------------------
// Pre-pass: 8 conv weight tensors -> tap-major zero-padded-3x3 fp16,
// plus flattened bias table.
// ---------------------------------------------------------------------------
__global__ void prep_weights_kernel(
    const float* __restrict__ w0, const float* __restrict__ w1,
    const float* __restrict__ w2, const float* __restrict__ w3,
    const float* __restrict__ w4, const float* __restrict__ w5,
    const float* __restrict__ w6, const float* __restrict__ w7,
    const float* __restrict__ b0, const float* __restrict__ b1,
    const float* __restrict__ b2, const float* __restrict__ b3,
    const float* __restrict__ b4, const float* __restrict__ b5,
    const float* __restrict__ b6, const float* __restrict__ b7)
{
    const int idx = blockIdx.x * 256 + threadIdx.x;   // 9*2048*512 elements
    const float* W[8] = {w0, w1, w2, w3, w4, w5, w6, w7};
    const float* B[8] = {b0, b1, b2, b3, b4, b5, b6, b7};
    const int KH[8] = {3, 2, 3, 2, 3, 2, 3, 2};
    const int KW[8] = {3, 3, 2, 2, 3, 3, 2, 2};

    if (idx < 2048) g_biasAll[idx] = B[idx >> 8][idx & 255];
    if (idx >= 9 * 2048 * 512) return;

    const int ci  = idx & 511;
    const int m   = (idx >> 9) & 2047;
    const int tap = idx >> 20;
    const int conv = m >> 8, co = m & 255;
    const int kh = tap / 3, kw = tap % 3;

    float v = 0.0f;
    if (kh < KH[conv] && kw < KW[conv])
        v = W[conv][((size_t)(co * CIN + ci) * KH[conv] + kh) * KW[conv] + kw];

    g_Wb[idx] = __float2half_rn(v);
}

__global__ void prep_w9_kernel(const float* __restrict__ w9)
{
    const int idx = blockIdx.x * 256 + threadIdx.x;   // 9*256*256
    if (idx >= 9 * 256 * 256) return;
    const int ci = idx & 255;
    const int co = (idx >> 8) & 255;
    const int tap = idx >> 16;
    const int kh = tap / 3, kw = tap % 3;
    float v = w9[((size_t)(co * CMID + ci) * 3 + kh) * 3 + kw];
    g_W9[idx] = __float2half_rn(v);
}

// ---------------------------------------------------------------------------
// mma.sync implicit-conv GEMM, fp16 x fp16 -> fp32 accum.
// CTA tile 128(M) x 128(N pixels), warp tile 64x32, K chunked by 64 channels
// at a fixed tap, cp.async 3-stage pipeline, 2 CTAs/SM.
// TAP SKIPPING: each phase-1 CTA covers one conv (128 of its 256 rows); it
// iterates only the KH*KW live taps of that conv — the zero-padded taps are
// never computed (exact no-op in the reference sum).
// PHASE2=false: A=g_Wb (M=2048), B=g_Xp, epilogue interleaves into Y1/Y2.
// PHASE2=true : A=g_W9 (M=256),  B=g_X2p, epilogue -> g_O1 (+b9).
// ---------------------------------------------------------------------------
template <int CIN_T, int WDIM, int ROWS, int MTOT, bool PHASE2>
__global__ __launch_bounds__(256, 2)
void gemm_kernel(const float* __restrict__ bias9)
{
    constexpr int HP = WDIM + 2, WP = WDIM + 2;
    constexpr int NT_PER_IMG = (WDIM * WDIM) / 128;
    constexpr int KCH = CIN_T / 64;
    constexpr int CI_SHIFT = (WDIM == 32) ? 5 : 6;
    // per-stage smem: A(16K) + B(16K) = 32KB; 3 stages = 96KB; 2 CTAs/SM.
    constexpr uint32_t BUF = 32768;

    extern __shared__ char smem[];
    const uint32_t sb = smem_u32(smem);

    const int tid  = threadIdx.x;
    const int wid  = tid >> 5;
    const int lane = tid & 31;
    const int m0   = blockIdx.x * 128;
    const int img  = blockIdx.y / NT_PER_IMG;
    const int i0   = (blockIdx.y % NT_PER_IMG) * ROWS;

    // ---- live-tap support for this CTA's conv ----
    int KH = 3, KW = 3;
    if (!PHASE2) {
        const int quad = (m0 >> 8) & 3;       // 0:(3,3) 1:(2,3) 2:(3,2) 3:(2,2)
        KH = (quad & 1) ? 2 : 3;
        KW = (quad & 2) ? 2 : 3;
    }
    const int NCHUNK = KH * KW * KCH;

    const float4* A4 = reinterpret_cast<const float4*>(PHASE2 ? g_W9 : g_Wb);
    const float4* B4 = reinterpret_cast<const float4*>(PHASE2 ? g_X2p : g_Xp);

    // ---- staging: 8 cp.async x 16B per thread per chunk ----
    auto stage = [&](int chunk, int buf) {
        const int tap_id = chunk / KCH;               // 0..KH*KW-1 (live taps only)
        const int ci0 = (chunk - tap_id * KCH) * 64;
        const int kh = tap_id / KW, kw = tap_id - kh * KW;
        const int tapA = kh * 3 + kw;                 // storage tap index (3x3 grid)
        const uint32_t bb = sb + buf * BUF;
#pragma unroll
        for (int it = 0; it < 4; ++it) {
            const int t = tid + it * 256;
            const int row = t >> 3, g = t & 7;
            const uint32_t off = sw128(row * 128 + g * 16);
            const long srcA = ((((long)(tapA * MTOT + m0 + row) * CIN_T + ci0)) >> 3) + g;
            CP16(bb + off, A4 + srcA);
            const int r = row >> CI_SHIFT, j = row & (WDIM - 1);
            const int y = i0 + r + kh, x = j + kw;
            const long srcB = ((((long)((img * HP + y) * WP + x) * CIN_T + ci0)) >> 3) + g;
            CP16(bb + 16384 + off, B4 + srcB);
        }
    };

    // ---- per-lane ldmatrix addressing components ----
    const int sub = lane >> 3, r8 = lane & 7;
    const int wm = wid & 1, wn = wid >> 1;
    const int arow_b = wm * 64 + ((sub & 1) << 3) + r8;   // + mt*16
    const int akoff  = (sub >> 1) << 4;
    const int brow_b = wn * 32 + ((sub >> 1) << 3) + r8;  // + q*16
    const int bkoff  = (sub & 1) << 4;

    float acc[4][4][4];
#pragma unroll
    for (int a = 0; a < 4; ++a)
#pragma unroll
        for (int b = 0; b < 4; ++b)
#pragma unroll
            for (int c = 0; c < 4; ++c) acc[a][b][c] = 0.0f;

    auto compute = [&](int buf) {
        const uint32_t AB = sb + buf * BUF;
        const uint32_t BB = AB + 16384;
#pragma unroll
        for (int kk = 0; kk < 4; ++kk) {
            uint32_t af[4][4], bf[4][2];
#pragma unroll
            for (int q = 0; q < 2; ++q) {
                const uint32_t ad = BB + sw128((brow_b + q * 16) * 128 + kk * 32 + bkoff);
                LDSM4(bf[2 * q][0], bf[2 * q][1], bf[2 * q + 1][0], bf[2 * q + 1][1], ad);
            }
#pragma unroll
            for (int mt = 0; mt < 4; ++mt) {
                const uint32_t ad = AB + sw128((arow_b + mt * 16) * 128 + kk * 32 + akoff);
                LDSM4(af[mt][0], af[mt][1], af[mt][2], af[mt][3], ad);
            }
#pragma unroll
            for (int mt = 0; mt < 4; ++mt)
#pragma unroll
                for (int nt = 0; nt < 4; ++nt)
                    MMA_F16(acc[mt][nt], af[mt], bf[nt]);
        }
    };

    // ---- 3-stage pipeline, one __syncthreads per chunk ----
    stage(0, 0); CP_COMMIT();
    stage(1, 1); CP_COMMIT();
    for (int c = 0; c < NCHUNK; ++c) {
        CP_WAIT1();            // chunk c landed
        __syncthreads();       // all warps done with compute(c-1); data visible
        if (c + 2 < NCHUNK) stage(c + 2, (c + 2) % 3);
        CP_COMMIT();
        compute(c % 3);
    }

    // ---- epilogue: scatter fragments to gmem with folded interleave ----
    const float* bias = PHASE2 ? bias9 : g_biasAll;
    int qr = 0, qc = 0, coBase = m0;
    float* Ybuf = g_O1;
    if (!PHASE2) {
        const int conv = m0 >> 8;
        const int quad = conv & 3;
        qr = quad & 1;
        qc = (quad >> 1) & 1;
        coBase = m0 & 255;
        Ybuf = (conv >= 4) ? g_Y2 : g_Y1;
    }

#pragma unroll
    for (int mt = 0; mt < 4; ++mt) {
        const int rowA = wm * 64 + mt * 16 + (lane >> 2);
        const float bv0 = bias[m0 + rowA];
        const float bv8 = bias[m0 + rowA + 8];
        const int co0 = coBase + rowA;
#pragma unroll
        for (int nt = 0; nt < 4; ++nt) {
            const int p = wn * 32 + nt * 8 + 2 * (lane & 3);
            int yy, xx, xstep;
            if (!PHASE2) {
                const int pr = p >> 5, pc = p & 31;
                yy = 2 * (i0 + pr) + qr;
                xx = 2 * pc + qc;
                xstep = 2;
            } else {
                const int pr = p >> 6, pc = p & 63;
                yy = i0 + pr;
                xx = pc;
                xstep = 1;
            }
            float* base0 = Ybuf + ((size_t)(img * CMID + co0) * HOUT + yy) * WOUT + xx;
            float* base8 = base0 + (size_t)8 * HOUT * WOUT;
            base0[0]     = acc[mt][nt][0] + bv0;
            base0[xstep] = acc[mt][nt][1] + bv0;
            base8[0]     = acc[mt][nt][2] + bv8;
            base8[xstep] = acc[mt][nt][3] + bv8;
        }
    }
}

// ---------------------------------------------------------------------------
// BN batch stats (biased, over N,H,W) -> folded affine (a, s).
// ---------------------------------------------------------------------------
__global__ void bn_stats_kernel(int which,
                                const float* __restrict__ gamma,
                                const float* __restrict__ beta)
{
    const int ch  = blockIdx.x;
    const int tid = threadIdx.x;
    const float* y = (which == 0) ? g_Y1 : (which == 1) ? g_Y2 : g_O1;
    float* A = (which == 0) ? g_a1 : (which == 1) ? g_a2 : g_a3;
    float* S = (which == 0) ? g_s1 : (which == 1) ? g_s2 : g_s3;

    float sum = 0.0f, sq = 0.0f;
    for (int idx = tid; idx < BATCH * 1024; idx += 256) {
        const int nn = idx >> 10;
        const int e4 = idx & 1023;
        const float4 v = reinterpret_cast<const float4*>(y + (size_t)(nn * CMID + ch) * 4096)[e4];
        sum += v.x + v.y + v.z + v.w;
        sq  += v.x * v.x + v.y * v.y + v.z * v.z + v.w * v.w;
    }
    __shared__ float rs[256], rq[256];
    rs[tid] = sum; rq[tid] = sq;
    __syncthreads();
    for (int off = 128; off > 0; off >>= 1) {
        if (tid < off) { rs[tid] += rs[tid + off]; rq[tid] += rq[tid + off]; }
        __syncthreads();
    }
    if (tid == 0) {
        const float inv = 1.0f / (float)(BATCH * HOUT * WOUT);
        const float mean = rs[0] * inv;
        const float var  = rq[0] * inv - mean * mean;
        const float a = gamma[ch] * rsqrtf(var + 1e-5f);
        A[ch] = a;
        S[ch] = beta[ch] - mean * a;
    }
}

// ---------------------------------------------------------------------------
// Final merge: out = relu( BN2(O1) + BN12(Y2) )
// ---------------------------------------------------------------------------
__global__ void final_kernel(float* __restrict__ out)
{
    const int idx = blockIdx.x * blockDim.x + threadIdx.x;
    if (idx >= NOUT / 4) return;
    const int c = (idx >> 10) & (CMID - 1);
    const float a2 = g_a2[c], s2 = g_s2[c];
    const float a3 = g_a3[c], s3 = g_s3[c];
    const float4 o = reinterpret_cast<const float4*>(g_O1)[idx];
    const float4 y = reinterpret_cast<const float4*>(g_Y2)[idx];
    float4 r;
    r.x = fmaxf(0.0f, fmaf(o.x, a3, s3) + fmaf(y.x, a2, s2));
    r.y = fmaxf(0.0f, fmaf(o.y, a3, s3) + fmaf(y.y, a2, s2));
    r.z = fmaxf(0.0f, fmaf(o.z, a3, s3) + fmaf(y.z, a2, s2));
    r.w = fmaxf(0.0f, fmaf(o.w, a3, s3) + fmaf(y.w, a2, s2));
    reinterpret_cast<float4*>(out)[idx] = r;
}

// ---------------------------------------------------------------------------
// Launch sequence
// ---------------------------------------------------------------------------
extern "C" void kernel_launch(void* const* d_in, const int* in_sizes, int n_in,
                              void* d_out, int out_size)
{
    const float* x   = (const float*)d_in[0];
    const float* w1  = (const float*)d_in[1];   const float* b1  = (const float*)d_in[2];
    const float* w2  = (const float*)d_in[3];   const float* b2  = (const float*)d_in[4];
    const float* w3  = (const float*)d_in[5];   const float* b3  = (const float*)d_in[6];
    const float* w4  = (const float*)d_in[7];   const float* b4  = (const float*)d_in[8];
    const float* w5  = (const float*)d_in[9];   const float* b5  = (const float*)d_in[10];
    const float* w6  = (const float*)d_in[11];  const float* b6  = (const float*)d_in[12];
    const float* w7  = (const float*)d_in[13];  const float* b7  = (const float*)d_in[14];
    const float* w8  = (const float*)d_in[15];  const float* b8  = (const float*)d_in[16];
    const float* w9  = (const float*)d_in[17];  const float* b9  = (const float*)d_in[18];
    const float* g11 = (const float*)d_in[19];  const float* be11 = (const float*)d_in[20];
    const float* g12 = (const float*)d_in[21];  const float* be12 = (const float*)d_in[22];
    const float* g2  = (const float*)d_in[23];  const float* be2  = (const float*)d_in[24];

    const int SMEM_GEMM = 3 * 32768;   // 98,304 B (3-stage pipeline, 2 CTAs/SM)
    cudaFuncSetAttribute(gemm_kernel<512, 32, 4, 2048, false>,
                         cudaFuncAttributeMaxDynamicSharedMemorySize, SMEM_GEMM);
    cudaFuncSetAttribute(gemm_kernel<256, 64, 2, 256, true>,
                         cudaFuncAttributeMaxDynamicSharedMemorySize, SMEM_GEMM);

    // Pre-passes: weights + input transform
    prep_weights_kernel<<<(9 * 2048 * 512) / 256, 256>>>(w1, w2, w3, w4, w5, w6, w7, w8,
                                                         b1, b2, b3, b4, b5, b6, b7, b8);
    prep_w9_kernel<<<(9 * 256 * 256) / 256, 256>>>(w9);
    pad_transpose_kernel<512, 32, false><<<BATCH * 34 * 8, 256>>>(x);

    // Phase-1 GEMM: all 8 unpool convs (M=2048, N=16 imgs x 1024 px),
    // each CTA iterates only its conv's live taps.
    gemm_kernel<512, 32, 4, 2048, false><<<dim3(16, 128), 256, SMEM_GEMM>>>(nullptr);

    bn_stats_kernel<<<CMID, 256>>>(0, g11, be11);   // BN11 (folded into phase-2 input)
    bn_stats_kernel<<<CMID, 256>>>(1, g12, be12);   // BN12 (folded into final)

    // relu(BN11(Y1)) -> padded transposed fp16
    pad_transpose_kernel<256, 64, true><<<BATCH * 66 * 4, 256>>>(nullptr);

    // Phase-2 GEMM: conv9 (M=256, N=16 imgs x 4096 px)
    gemm_kernel<256, 64, 2, 256, true><<<dim3(2, 512), 256, SMEM_GEMM>>>(b9);

    bn_stats_kernel<<<CMID, 256>>>(2, g2, be2);     // BN2 (folded into final)
    final_kernel<<<(NOUT / 4 + 255) / 256, 256>>>((float*)d_out);
}

// round 10
// speedup vs baseline: 8.6322x; 1.1099x over previous
#include <cuda_runtime.h>
#include <cuda_fp16.h>
#include <cstdint>

// ---------------------------------------------------------------------------
// Problem constants
// ---------------------------------------------------------------------------
#define BATCH 16
#define CIN   512
#define CMID  256
#define HOUT  64
#define WOUT  64
#define NOUT  (BATCH * CMID * HOUT * WOUT)   // 16,777,216

// ---------------------------------------------------------------------------
// Device-global scratch (no allocations allowed)
// ---------------------------------------------------------------------------
__device__ float g_Y1[NOUT];                 // branch-1 interleaved output (pre-BN)
__device__ float g_Y2[NOUT];                 // branch-2 interleaved output
__device__ float g_O1[NOUT];                 // conv9 output (pre-BN)
__device__ float g_a1[CMID], g_s1[CMID];
__device__ float g_a2[CMID], g_s2[CMID];
__device__ float g_a3[CMID], g_s3[CMID];
__device__ float g_biasAll[2048];

// Padded, channel-innermost activations (fp16)
__device__ __half g_Xp [BATCH * 34 * 34 * CIN];
__device__ __half g_X2p[BATCH * 66 * 66 * CMID];

// Tap-major weights (fp16, zero-padded to 3x3): [tap][M][Cin]
__device__ __half g_Wb[9 * 2048 * CIN];
__device__ __half g_W9[9 * 256 * CMID];

// ---------------------------------------------------------------------------
// Helpers (base sm_80+ features only — valid on plain sm_103 target)
// ---------------------------------------------------------------------------
__device__ __forceinline__ uint32_t smem_u32(const void* p) {
    uint32_t a;
    asm("{ .reg .u64 t; cvta.to.shared.u64 t, %1; cvt.u32.u64 %0, t; }" : "=r"(a) : "l"(p));
    return a;
}
__device__ __forceinline__ uint32_t sw128(uint32_t off) { return off ^ ((off >> 3) & 0x70); }

#define CP16(saddr, gptr) \
    asm volatile("cp.async.cg.shared.global [%0], [%1], 16;" :: "r"(saddr), "l"(gptr))
#define CP_COMMIT() asm volatile("cp.async.commit_group;" ::: "memory")
#define CP_WAIT1()  asm volatile("cp.async.wait_group 1;" ::: "memory")

#define LDSM4(r0, r1, r2, r3, addr) \
    asm volatile("ldmatrix.sync.aligned.m8n8.x4.shared.b16 {%0,%1,%2,%3}, [%4];" \
                 : "=r"(r0), "=r"(r1), "=r"(r2), "=r"(r3) : "r"(addr))

#define MMA_F16(d, a, b) \
    asm volatile("mma.sync.aligned.m16n8k16.row.col.f32.f16.f16.f32 " \
                 "{%0,%1,%2,%3}, {%4,%5,%6,%7}, {%8,%9}, {%0,%1,%2,%3};" \
                 : "+f"((d)[0]), "+f"((d)[1]), "+f"((d)[2]), "+f"((d)[3]) \
                 : "r"((a)[0]), "r"((a)[1]), "r"((a)[2]), "r"((a)[3]),   \
                   "r"((b)[0]), "r"((b)[1]))

// ---------------------------------------------------------------------------
// Pre-pass: pad + transpose to channel-innermost + fp16 convert.
// ---------------------------------------------------------------------------
template <int C, int H, bool AFFINE>
__global__ void pad_transpose_kernel(const float* __restrict__ src_arg)
{
    constexpr int HP = H + 2, WP = H + 2;
    constexpr int CB = C / 64;
    __shared__ float sm[64][H + 1];

    const int bid = blockIdx.x;
    const int cb  = bid % CB;
    const int y   = (bid / CB) % HP;
    const int img = bid / (CB * HP);
    const int tid = threadIdx.x;

    const float* src = AFFINE ? (const float*)g_Y1 : src_arg;
    __half* oh = (AFFINE ? g_X2p : g_Xp) + ((size_t)(img * HP + y)) * WP * C + cb * 64;

    if (y == 0 || y == HP - 1) {
        for (int t = tid; t < WP * 64; t += 256) {
            int x = t >> 6, ci = t & 63;
            oh[(size_t)x * C + ci] = __float2half_rn(0.0f);
        }
        return;
    }

    for (int t = tid; t < 64 * H; t += 256) {
        int ci = t / H, x = t % H;
        int ch = cb * 64 + ci;
        float v = src[((size_t)(img * C + ch) * H + (y - 1)) * H + x];
        if (AFFINE) v = fmaxf(0.0f, fmaf(v, g_a1[ch], g_s1[ch]));
        sm[ci][x] = v;
    }
    __syncthreads();

    for (int t = tid; t < WP * 64; t += 256) {
        int x = t >> 6, ci = t & 63;
        float v = (x >= 1 && x <= H) ? sm[ci][x - 1] : 0.0f;
        oh[(size_t)x * C + ci] = __float2half_rn(v);
    }
}

// ---------------------------------------------------------------------------
// Pre-pass: 8 conv weight tensors -> tap-major zero-padded-3x3 fp16 + biases.
// ---------------------------------------------------------------------------
__global__ void prep_weights_kernel(
    const float* __restrict__ w0, const float* __restrict__ w1,
    const float* __restrict__ w2, const float* __restrict__ w3,
    const float* __restrict__ w4, const float* __restrict__ w5,
    const float* __restrict__ w6, const float* __restrict__ w7,
    const float* __restrict__ b0, const float* __restrict__ b1,
    const float* __restrict__ b2, const float* __restrict__ b3,
    const float* __restrict__ b4, const float* __restrict__ b5,
    const float* __restrict__ b6, const float* __restrict__ b7)
{
    const int idx = blockIdx.x * 256 + threadIdx.x;   // 9*2048*512 elements
    const float* W[8] = {w0, w1, w2, w3, w4, w5, w6, w7};
    const float* B[8] = {b0, b1, b2, b3, b4, b5, b6, b7};
    const int KH[8] = {3, 2, 3, 2, 3, 2, 3, 2};
    const int KW[8] = {3, 3, 2, 2, 3, 3, 2, 2};

    if (idx < 2048) g_biasAll[idx] = B[idx >> 8][idx & 255];
    if (idx >= 9 * 2048 * 512) return;

    const int ci  = idx & 511;
    const int m   = (idx >> 9) & 2047;
    const int tap = idx >> 20;
    const int conv = m >> 8, co = m & 255;
    const int kh = tap / 3, kw = tap % 3;

    float v = 0.0f;
    if (kh < KH[conv] && kw < KW[conv])
        v = W[conv][((size_t)(co * CIN + ci) * KH[conv] + kh) * KW[conv] + kw];

    g_Wb[idx] = __float2half_rn(v);
}

__global__ void prep_w9_kernel(const float* __restrict__ w9)
{
    const int idx = blockIdx.x * 256 + threadIdx.x;   // 9*256*256
    if (idx >= 9 * 256 * 256) return;
    const int ci = idx & 255;
    const int co = (idx >> 8) & 255;
    const int tap = idx >> 16;
    const int kh = tap / 3, kw = tap % 3;
    float v = w9[((size_t)(co * CMID + ci) * 3 + kh) * 3 + kw];
    g_W9[idx] = __float2half_rn(v);
}

// ---------------------------------------------------------------------------
// Templated mainloop: compile-time KH/KW -> no divisions, full unrolling.
// CTA tile 128(M) x 128(N pixels), warp tile 64x32, K chunked by 64 channels
// at a fixed live tap, cp.async 3-stage pipeline, 2 CTAs/SM.
// ---------------------------------------------------------------------------
template <int KH, int KW, int CIN_T, int WDIM, int ROWS, int MTOT, bool PHASE2>
__device__ __forceinline__ void run_gemm(
    uint32_t sb, int tid, int wid, int lane,
    int m0, int img, int i0, const float* __restrict__ bias9)
{
    constexpr int HP = WDIM + 2, WP = WDIM + 2;
    constexpr int KCH = CIN_T / 64;
    constexpr int NCHUNK = KH * KW * KCH;
    constexpr int CI_SHIFT = (WDIM == 32) ? 5 : 6;
    constexpr uint32_t BUF = 32768;

    const float4* A4 = reinterpret_cast<const float4*>(PHASE2 ? g_W9 : g_Wb);
    const float4* B4 = reinterpret_cast<const float4*>(PHASE2 ? g_X2p : g_Xp);

    // ---- staging: 8 cp.async x 16B per thread per chunk ----
    auto stage = [&](int chunk, int buf) {
        const int tap_id = chunk / KCH;               // constexpr KCH -> shift
        const int ci0 = (chunk - tap_id * KCH) * 64;
        const int kh = tap_id / KW, kw = tap_id - kh * KW;  // constexpr KW
        const int tapA = kh * 3 + kw;                 // storage tap index (3x3 grid)
        const uint32_t bb = sb + buf * BUF;
#pragma unroll
        for (int it = 0; it < 4; ++it) {
            const int t = tid + it * 256;
            const int row = t >> 3, g = t & 7;
            const uint32_t off = sw128(row * 128 + g * 16);
            const long srcA = ((((long)(tapA * MTOT + m0 + row) * CIN_T + ci0)) >> 3) + g;
            CP16(bb + off, A4 + srcA);
            const int r = row >> CI_SHIFT, j = row & (WDIM - 1);
            const int y = i0 + r + kh, x = j + kw;
            const long srcB = ((((long)((img * HP + y) * WP + x) * CIN_T + ci0)) >> 3) + g;
            CP16(bb + 16384 + off, B4 + srcB);
        }
    };

    // ---- per-lane ldmatrix addressing components ----
    const int sub = lane >> 3, r8 = lane & 7;
    const int wm = wid & 1, wn = wid >> 1;
    const int arow_b = wm * 64 + ((sub & 1) << 3) + r8;   // + mt*16
    const int akoff  = (sub >> 1) << 4;
    const int brow_b = wn * 32 + ((sub >> 1) << 3) + r8;  // + q*16
    const int bkoff  = (sub & 1) << 4;

    float acc[4][4][4];
#pragma unroll
    for (int a = 0; a < 4; ++a)
#pragma unroll
        for (int b = 0; b < 4; ++b)
#pragma unroll
            for (int c = 0; c < 4; ++c) acc[a][b][c] = 0.0f;

    auto compute = [&](int buf) {
        const uint32_t AB = sb + buf * BUF;
        const uint32_t BB = AB + 16384;
#pragma unroll
        for (int kk = 0; kk < 4; ++kk) {
            uint32_t af[4][4], bf[4][2];
#pragma unroll
            for (int q = 0; q < 2; ++q) {
                const uint32_t ad = BB + sw128((brow_b + q * 16) * 128 + kk * 32 + bkoff);
                LDSM4(bf[2 * q][0], bf[2 * q][1], bf[2 * q + 1][0], bf[2 * q + 1][1], ad);
            }
#pragma unroll
            for (int mt = 0; mt < 4; ++mt) {
                const uint32_t ad = AB + sw128((arow_b + mt * 16) * 128 + kk * 32 + akoff);
                LDSM4(af[mt][0], af[mt][1], af[mt][2], af[mt][3], ad);
            }
#pragma unroll
            for (int mt = 0; mt < 4; ++mt)
#pragma unroll
                for (int nt = 0; nt < 4; ++nt)
                    MMA_F16(acc[mt][nt], af[mt], bf[nt]);
        }
    };

    // ---- 3-stage pipeline, one __syncthreads per chunk ----
    stage(0, 0); CP_COMMIT();
    stage(1, 1); CP_COMMIT();
    for (int c = 0; c < NCHUNK; ++c) {
        CP_WAIT1();            // chunk c landed
        __syncthreads();       // all warps done with compute(c-1); data visible
        if (c + 2 < NCHUNK) stage(c + 2, (c + 2) % 3);
        CP_COMMIT();
        compute(c % 3);
    }

    // ---- epilogue: scatter fragments to gmem with folded interleave ----
    const float* bias = PHASE2 ? bias9 : g_biasAll;
    int qr = 0, qc = 0, coBase = m0;
    float* Ybuf = g_O1;
    if (!PHASE2) {
        const int conv = m0 >> 8;
        const int quad = conv & 3;
        qr = quad & 1;
        qc = (quad >> 1) & 1;
        coBase = m0 & 255;
        Ybuf = (conv >= 4) ? g_Y2 : g_Y1;
    }

#pragma unroll
    for (int mt = 0; mt < 4; ++mt) {
        const int rowA = wm * 64 + mt * 16 + (lane >> 2);
        const float bv0 = bias[m0 + rowA];
        const float bv8 = bias[m0 + rowA + 8];
        const int co0 = coBase + rowA;
#pragma unroll
        for (int nt = 0; nt < 4; ++nt) {
            const int p = wn * 32 + nt * 8 + 2 * (lane & 3);
            int yy, xx, xstep;
            if (!PHASE2) {
                const int pr = p >> 5, pc = p & 31;
                yy = 2 * (i0 + pr) + qr;
                xx = 2 * pc + qc;
                xstep = 2;
            } else {
                const int pr = p >> 6, pc = p & 63;
                yy = i0 + pr;
                xx = pc;
                xstep = 1;
            }
            float* base0 = Ybuf + ((size_t)(img * CMID + co0) * HOUT + yy) * WOUT + xx;
            float* base8 = base0 + (size_t)8 * HOUT * WOUT;
            base0[0]     = acc[mt][nt][0] + bv0;
            base0[xstep] = acc[mt][nt][1] + bv0;
            base8[0]     = acc[mt][nt][2] + bv8;
            base8[xstep] = acc[mt][nt][3] + bv8;
        }
    }
}

// ---------------------------------------------------------------------------
// Kernel wrappers: constexpr tap dispatch per CTA (phase 1) / fixed 3x3 (phase 2)
// ---------------------------------------------------------------------------
template <int CIN_T, int WDIM, int ROWS, int MTOT, bool PHASE2>
__global__ __launch_bounds__(256, 2)
void gemm_kernel(const float* __restrict__ bias9)
{
    constexpr int NT_PER_IMG = (WDIM * WDIM) / 128;
    extern __shared__ char smem[];
    const uint32_t sb = smem_u32(smem);

    const int tid  = threadIdx.x;
    const int wid  = tid >> 5;
    const int lane = tid & 31;
    const int m0   = blockIdx.x * 128;
    const int img  = blockIdx.y / NT_PER_IMG;
    const int i0   = (blockIdx.y % NT_PER_IMG) * ROWS;

    if (PHASE2) {
        run_gemm<3, 3, CIN_T, WDIM, ROWS, MTOT, PHASE2>(sb, tid, wid, lane, m0, img, i0, bias9);
    } else {
        switch ((m0 >> 8) & 3) {   // 0:(3,3) 1:(2,3) 2:(3,2) 3:(2,2)
        case 0: run_gemm<3, 3, CIN_T, WDIM, ROWS, MTOT, PHASE2>(sb, tid, wid, lane, m0, img, i0, bias9); break;
        case 1: run_gemm<2, 3, CIN_T, WDIM, ROWS, MTOT, PHASE2>(sb, tid, wid, lane, m0, img, i0, bias9); break;
        case 2: run_gemm<3, 2, CIN_T, WDIM, ROWS, MTOT, PHASE2>(sb, tid, wid, lane, m0, img, i0, bias9); break;
        default: run_gemm<2, 2, CIN_T, WDIM, ROWS, MTOT, PHASE2>(sb, tid, wid, lane, m0, img, i0, bias9); break;
        }
    }
}

// ---------------------------------------------------------------------------
// BN batch stats (biased, over N,H,W) -> folded affine (a, s).
// grid = (CMID, n) ; blockIdx.y selects which buffer via base index.
// ---------------------------------------------------------------------------
__global__ void bn_stats_kernel(int which0,
                                const float* __restrict__ gammaA, const float* __restrict__ betaA,
                                const float* __restrict__ gammaB, const float* __restrict__ betaB)
{
    const int which = which0 + blockIdx.y;
    const int ch  = blockIdx.x;
    const int tid = threadIdx.x;
    const float* y = (which == 0) ? g_Y1 : (which == 1) ? g_Y2 : g_O1;
    float* A = (which == 0) ? g_a1 : (which == 1) ? g_a2 : g_a3;
    float* S = (which == 0) ? g_s1 : (which == 1) ? g_s2 : g_s3;
    const float* gamma = blockIdx.y ? gammaB : gammaA;
    const float* beta  = blockIdx.y ? betaB  : betaA;

    float sum = 0.0f, sq = 0.0f;
    for (int idx = tid; idx < BATCH * 1024; idx += 256) {
        const int nn = idx >> 10;
        const int e4 = idx & 1023;
        const float4 v = reinterpret_cast<const float4*>(y + (size_t)(nn * CMID + ch) * 4096)[e4];
        sum += v.x + v.y + v.z + v.w;
        sq  += v.x * v.x + v.y * v.y + v.z * v.z + v.w * v.w;
    }
    __shared__ float rs[256], rq[256];
    rs[tid] = sum; rq[tid] = sq;
    __syncthreads();
    for (int off = 128; off > 0; off >>= 1) {
        if (tid < off) { rs[tid] += rs[tid + off]; rq[tid] += rq[tid + off]; }
        __syncthreads();
    }
    if (tid == 0) {
        const float inv = 1.0f / (float)(BATCH * HOUT * WOUT);
        const float mean = rs[0] * inv;
        const float var  = rq[0] * inv - mean * mean;
        const float a = gamma[ch] * rsqrtf(var + 1e-5f);
        A[ch] = a;
        S[ch] = beta[ch] - mean * a;
    }
}

// ---------------------------------------------------------------------------
// Final merge: out = relu( BN2(O1) + BN12(Y2) )
// ---------------------------------------------------------------------------
__global__ void final_kernel(float* __restrict__ out)
{
    const int idx = blockIdx.x * blockDim.x + threadIdx.x;
    if (idx >= NOUT / 4) return;
    const int c = (idx >> 10) & (CMID - 1);
    const float a2 = g_a2[c], s2 = g_s2[c];
    const float a3 = g_a3[c], s3 = g_s3[c];
    const float4 o = reinterpret_cast<const float4*>(g_O1)[idx];
    const float4 y = reinterpret_cast<const float4*>(g_Y2)[idx];
    float4 r;
    r.x = fmaxf(0.0f, fmaf(o.x, a3, s3) + fmaf(y.x, a2, s2));
    r.y = fmaxf(0.0f, fmaf(o.y, a3, s3) + fmaf(y.y, a2, s2));
    r.z = fmaxf(0.0f, fmaf(o.z, a3, s3) + fmaf(y.z, a2, s2));
    r.w = fmaxf(0.0f, fmaf(o.w, a3, s3) + fmaf(y.w, a2, s2));
    reinterpret_cast<float4*>(out)[idx] = r;
}

// ---------------------------------------------------------------------------
// Launch sequence
// ---------------------------------------------------------------------------
extern "C" void kernel_launch(void* const* d_in, const int* in_sizes, int n_in,
                              void* d_out, int out_size)
{
    const float* x   = (const float*)d_in[0];
    const float* w1  = (const float*)d_in[1];   const float* b1  = (const float*)d_in[2];
    const float* w2  = (const float*)d_in[3];   const float* b2  = (const float*)d_in[4];
    const float* w3  = (const float*)d_in[5];   const float* b3  = (const float*)d_in[6];
    const float* w4  = (const float*)d_in[7];   const float* b4  = (const float*)d_in[8];
    const float* w5  = (const float*)d_in[9];   const float* b5  = (const float*)d_in[10];
    const float* w6  = (const float*)d_in[11];  const float* b6  = (const float*)d_in[12];
    const float* w7  = (const float*)d_in[13];  const float* b7  = (const float*)d_in[14];
    const float* w8  = (const float*)d_in[15];  const float* b8  = (const float*)d_in[16];
    const float* w9  = (const float*)d_in[17];  const float* b9  = (const float*)d_in[18];
    const float* g11 = (const float*)d_in[19];  const float* be11 = (const float*)d_in[20];
    const float* g12 = (const float*)d_in[21];  const float* be12 = (const float*)d_in[22];
    const float* g2  = (const float*)d_in[23];  const float* be2  = (const float*)d_in[24];

    const int SMEM_GEMM = 3 * 32768;   // 98,304 B (3-stage pipeline, 2 CTAs/SM)
    cudaFuncSetAttribute(gemm_kernel<512, 32, 4, 2048, false>,
                         cudaFuncAttributeMaxDynamicSharedMemorySize, SMEM_GEMM);
    cudaFuncSetAttribute(gemm_kernel<256, 64, 2, 256, true>,
                         cudaFuncAttributeMaxDynamicSharedMemorySize, SMEM_GEMM);

    // Pre-passes: weights + input transform
    prep_weights_kernel<<<(9 * 2048 * 512) / 256, 256>>>(w1, w2, w3, w4, w5, w6, w7, w8,
                                                         b1, b2, b3, b4, b5, b6, b7, b8);
    prep_w9_kernel<<<(9 * 256 * 256) / 256, 256>>>(w9);
    pad_transpose_kernel<512, 32, false><<<BATCH * 34 * 8, 256>>>(x);

    // Phase-1 GEMM: all 8 unpool convs; constexpr live-tap dispatch per CTA.
    gemm_kernel<512, 32, 4, 2048, false><<<dim3(16, 128), 256, SMEM_GEMM>>>(nullptr);

    // BN11 + BN12 stats in one launch
    bn_stats_kernel<<<dim3(CMID, 2), 256>>>(0, g11, be11, g12, be12);

    // relu(BN11(Y1)) -> padded transposed fp16
    pad_transpose_kernel<256, 64, true><<<BATCH * 66 * 4, 256>>>(nullptr);

    // Phase-2 GEMM: conv9
    gemm_kernel<256, 64, 2, 256, true><<<dim3(2, 512), 256, SMEM_GEMM>>>(b9);

    // BN2 stats
    bn_stats_kernel<<<dim3(CMID, 1), 256>>>(2, g2, be2, g2, be2);
    final_kernel<<<(NOUT / 4 + 255) / 256, 256>>>((float*)d_out);
}

// round 11
// speedup vs baseline: 8.8673x; 1.0272x over previous
#include <cuda_runtime.h>
#include <cuda_fp16.h>
#include <cstdint>

// ---------------------------------------------------------------------------
// Problem constants
// ---------------------------------------------------------------------------
#define BATCH 16
#define CIN   512
#define CMID  256
#define HOUT  64
#define WOUT  64
#define NOUT  (BATCH * CMID * HOUT * WOUT)   // 16,777,216

// ---------------------------------------------------------------------------
// Device-global scratch (no allocations allowed)
// ---------------------------------------------------------------------------
__device__ float g_Y1[NOUT];                 // branch-1 interleaved output (pre-BN)
__device__ float g_Y2[NOUT];                 // branch-2 interleaved output
__device__ float g_O1[NOUT];                 // conv9 output (pre-BN)
__device__ float g_a1[CMID], g_s1[CMID];
__device__ float g_a2[CMID], g_s2[CMID];
__device__ float g_a3[CMID], g_s3[CMID];
__device__ float g_biasAll[2048];

// Deterministic BN partials: [slot][ch] (sum, sumsq)
__device__ float2 g_part1[2048 * 128];       // phase-1 CTAs (2 MB)
__device__ float2 g_part2[1024 * 128];       // phase-2 CTAs (1 MB)

// Padded, channel-innermost activations (fp16)
__device__ __half g_Xp [BATCH * 34 * 34 * CIN];
__device__ __half g_X2p[BATCH * 66 * 66 * CMID];

// Tap-major weights (fp16, zero-padded to 3x3): [tap][M][Cin]
__device__ __half g_Wb[9 * 2048 * CIN];
__device__ __half g_W9[9 * 256 * CMID];

// ---------------------------------------------------------------------------
// Helpers (base sm_80+ features only — valid on plain sm_103 target)
// ---------------------------------------------------------------------------
__device__ __forceinline__ uint32_t smem_u32(const void* p) {
    uint32_t a;
    asm("{ .reg .u64 t; cvta.to.shared.u64 t, %1; cvt.u32.u64 %0, t; }" : "=r"(a) : "l"(p));
    return a;
}
__device__ __forceinline__ uint32_t sw128(uint32_t off) { return off ^ ((off >> 3) & 0x70); }

#define CP16(saddr, gptr) \
    asm volatile("cp.async.cg.shared.global [%0], [%1], 16;" :: "r"(saddr), "l"(gptr))
#define CP_COMMIT() asm volatile("cp.async.commit_group;" ::: "memory")
#define CP_WAIT1()  asm volatile("cp.async.wait_group 1;" ::: "memory")

#define LDSM4(r0, r1, r2, r3, addr) \
    asm volatile("ldmatrix.sync.aligned.m8n8.x4.shared.b16 {%0,%1,%2,%3}, [%4];" \
                 : "=r"(r0), "=r"(r1), "=r"(r2), "=r"(r3) : "r"(addr))

#define MMA_F16(d, a, b) \
    asm volatile("mma.sync.aligned.m16n8k16.row.col.f32.f16.f16.f32 " \
                 "{%0,%1,%2,%3}, {%4,%5,%6,%7}, {%8,%9}, {%0,%1,%2,%3};" \
                 : "+f"((d)[0]), "+f"((d)[1]), "+f"((d)[2]), "+f"((d)[3]) \
                 : "r"((a)[0]), "r"((a)[1]), "r"((a)[2]), "r"((a)[3]),   \
                   "r"((b)[0]), "r"((b)[1]))

// ---------------------------------------------------------------------------
// Pre-pass: pad + transpose to channel-innermost + fp16 convert.
// ---------------------------------------------------------------------------
template <int C, int H, bool AFFINE>
__global__ void pad_transpose_kernel(const float* __restrict__ src_arg)
{
    constexpr int HP = H + 2, WP = H + 2;
    constexpr int CB = C / 64;
    __shared__ float sm[64][H + 1];

    const int bid = blockIdx.x;
    const int cb  = bid % CB;
    const int y   = (bid / CB) % HP;
    const int img = bid / (CB * HP);
    const int tid = threadIdx.x;

    const float* src = AFFINE ? (const float*)g_Y1 : src_arg;
    __half* oh = (AFFINE ? g_X2p : g_Xp) + ((size_t)(img * HP + y)) * WP * C + cb * 64;

    if (y == 0 || y == HP - 1) {
        for (int t = tid; t < WP * 64; t += 256) {
            int x = t >> 6, ci = t & 63;
            oh[(size_t)x * C + ci] = __float2half_rn(0.0f);
        }
        return;
    }

    for (int t = tid; t < 64 * H; t += 256) {
        int ci = t / H, x = t % H;
        int ch = cb * 64 + ci;
        float v = src[((size_t)(img * C + ch) * H + (y - 1)) * H + x];
        if (AFFINE) v = fmaxf(0.0f, fmaf(v, g_a1[ch], g_s1[ch]));
        sm[ci][x] = v;
    }
    __syncthreads();

    for (int t = tid; t < WP * 64; t += 256) {
        int x = t >> 6, ci = t & 63;
        float v = (x >= 1 && x <= H) ? sm[ci][x - 1] : 0.0f;
        oh[(size_t)x * C + ci] = __float2half_rn(v);
    }
}

// ---------------------------------------------------------------------------
// Pre-pass: 8 unpool conv weights + conv9 weights -> tap-major zero-padded
// 3x3 fp16, plus flattened bias table.  (merged into one launch)
// ---------------------------------------------------------------------------
__global__ void prep_weights_kernel(
    const float* __restrict__ w0, const float* __restrict__ w1,
    const float* __restrict__ w2, const float* __restrict__ w3,
    const float* __restrict__ w4, const float* __restrict__ w5,
    const float* __restrict__ w6, const float* __restrict__ w7,
    const float* __restrict__ b0, const float* __restrict__ b1,
    const float* __restrict__ b2, const float* __restrict__ b3,
    const float* __restrict__ b4, const float* __restrict__ b5,
    const float* __restrict__ b6, const float* __restrict__ b7,
    const float* __restrict__ w9)
{
    const int idx = blockIdx.x * 256 + threadIdx.x;
    const float* W[8] = {w0, w1, w2, w3, w4, w5, w6, w7};
    const float* B[8] = {b0, b1, b2, b3, b4, b5, b6, b7};
    const int KH[8] = {3, 2, 3, 2, 3, 2, 3, 2};
    const int KW[8] = {3, 3, 2, 2, 3, 3, 2, 2};

    if (idx < 2048) g_biasAll[idx] = B[idx >> 8][idx & 255];

    if (idx < 9 * 2048 * 512) {
        const int ci  = idx & 511;
        const int m   = (idx >> 9) & 2047;
        const int tap = idx >> 20;
        const int conv = m >> 8, co = m & 255;
        const int kh = tap / 3, kw = tap % 3;
        float v = 0.0f;
        if (kh < KH[conv] && kw < KW[conv])
            v = W[conv][((size_t)(co * CIN + ci) * KH[conv] + kh) * KW[conv] + kw];
        g_Wb[idx] = __float2half_rn(v);
        return;
    }
    const int j = idx - 9 * 2048 * 512;      // conv9 block: 9*256*256
    if (j >= 9 * 256 * 256) return;
    const int ci = j & 255;
    const int co = (j >> 8) & 255;
    const int tap = j >> 16;
    const int kh = tap / 3, kw = tap % 3;
    float v = w9[((size_t)(co * CMID + ci) * 3 + kh) * 3 + kw];
    g_W9[j] = __float2half_rn(v);
}

// ---------------------------------------------------------------------------
// Templated mainloop: compile-time KH/KW -> no divisions, full unrolling.
// CTA tile 128(M) x 128(N pixels), warp tile 64x32, K chunked by 64 channels
// at a fixed live tap, cp.async 3-stage pipeline, 2 CTAs/SM.
// Epilogue also emits deterministic per-CTA BN partials (sum, sumsq).
// ---------------------------------------------------------------------------
template <int KH, int KW, int CIN_T, int WDIM, int ROWS, int MTOT, bool PHASE2>
__device__ __forceinline__ void run_gemm(
    char* smem_c, uint32_t sb, int tid, int wid, int lane,
    int m0, int img, int i0, const float* __restrict__ bias9)
{
    constexpr int HP = WDIM + 2, WP = WDIM + 2;
    constexpr int KCH = CIN_T / 64;
    constexpr int NCHUNK = KH * KW * KCH;
    constexpr int CI_SHIFT = (WDIM == 32) ? 5 : 6;
    constexpr uint32_t BUF = 32768;

    const float4* A4 = reinterpret_cast<const float4*>(PHASE2 ? g_W9 : g_Wb);
    const float4* B4 = reinterpret_cast<const float4*>(PHASE2 ? g_X2p : g_Xp);

    // ---- staging: 8 cp.async x 16B per thread per chunk ----
    auto stage = [&](int chunk, int buf) {
        const int tap_id = chunk / KCH;
        const int ci0 = (chunk - tap_id * KCH) * 64;
        const int kh = tap_id / KW, kw = tap_id - kh * KW;
        const int tapA = kh * 3 + kw;                 // storage tap index (3x3 grid)
        const uint32_t bb = sb + buf * BUF;
#pragma unroll
        for (int it = 0; it < 4; ++it) {
            const int t = tid + it * 256;
            const int row = t >> 3, g = t & 7;
            const uint32_t off = sw128(row * 128 + g * 16);
            const long srcA = ((((long)(tapA * MTOT + m0 + row) * CIN_T + ci0)) >> 3) + g;
            CP16(bb + off, A4 + srcA);
            const int r = row >> CI_SHIFT, j = row & (WDIM - 1);
            const int y = i0 + r + kh, x = j + kw;
            const long srcB = ((((long)((img * HP + y) * WP + x) * CIN_T + ci0)) >> 3) + g;
            CP16(bb + 16384 + off, B4 + srcB);
        }
    };

    // ---- per-lane ldmatrix addressing components ----
    const int sub = lane >> 3, r8 = lane & 7;
    const int wm = wid & 1, wn = wid >> 1;
    const int arow_b = wm * 64 + ((sub & 1) << 3) + r8;   // + mt*16
    const int akoff  = (sub >> 1) << 4;
    const int brow_b = wn * 32 + ((sub >> 1) << 3) + r8;  // + q*16
    const int bkoff  = (sub & 1) << 4;

    float acc[4][4][4];
#pragma unroll
    for (int a = 0; a < 4; ++a)
#pragma unroll
        for (int b = 0; b < 4; ++b)
#pragma unroll
            for (int c = 0; c < 4; ++c) acc[a][b][c] = 0.0f;

    auto compute = [&](int buf) {
        const uint32_t AB = sb + buf * BUF;
        const uint32_t BB = AB + 16384;
#pragma unroll
        for (int kk = 0; kk < 4; ++kk) {
            uint32_t af[4][4], bf[4][2];
#pragma unroll
            for (int q = 0; q < 2; ++q) {
                const uint32_t ad = BB + sw128((brow_b + q * 16) * 128 + kk * 32 + bkoff);
                LDSM4(bf[2 * q][0], bf[2 * q][1], bf[2 * q + 1][0], bf[2 * q + 1][1], ad);
            }
#pragma unroll
            for (int mt = 0; mt < 4; ++mt) {
                const uint32_t ad = AB + sw128((arow_b + mt * 16) * 128 + kk * 32 + akoff);
                LDSM4(af[mt][0], af[mt][1], af[mt][2], af[mt][3], ad);
            }
#pragma unroll
            for (int mt = 0; mt < 4; ++mt)
#pragma unroll
                for (int nt = 0; nt < 4; ++nt)
                    MMA_F16(acc[mt][nt], af[mt], bf[nt]);
        }
    };

    // ---- 3-stage pipeline, one __syncthreads per chunk ----
    stage(0, 0); CP_COMMIT();
    stage(1, 1); CP_COMMIT();
    for (int c = 0; c < NCHUNK; ++c) {
        CP_WAIT1();            // chunk c landed
        __syncthreads();       // all warps done with compute(c-1); data visible
        if (c + 2 < NCHUNK) stage(c + 2, (c + 2) % 3);
        CP_COMMIT();
        compute(c % 3);
    }

    // ---- epilogue: scatter + per-thread BN partial accumulation ----
    const float* bias = PHASE2 ? bias9 : g_biasAll;
    int qr = 0, qc = 0, coBase = m0;
    float* Ybuf = g_O1;
    if (!PHASE2) {
        const int conv = m0 >> 8;
        const int quad = conv & 3;
        qr = quad & 1;
        qc = (quad >> 1) & 1;
        coBase = m0 & 255;
        Ybuf = (conv >= 4) ? g_Y2 : g_Y1;
    }

    float tsum[4][2], tsq[4][2];
#pragma unroll
    for (int mt = 0; mt < 4; ++mt) { tsum[mt][0] = tsum[mt][1] = tsq[mt][0] = tsq[mt][1] = 0.0f; }

#pragma unroll
    for (int mt = 0; mt < 4; ++mt) {
        const int rowA = wm * 64 + mt * 16 + (lane >> 2);
        const float bv0 = bias[m0 + rowA];
        const float bv8 = bias[m0 + rowA + 8];
        const int co0 = coBase + rowA;
#pragma unroll
        for (int nt = 0; nt < 4; ++nt) {
            const int p = wn * 32 + nt * 8 + 2 * (lane & 3);
            int yy, xx, xstep;
            if (!PHASE2) {
                const int pr = p >> 5, pc = p & 31;
                yy = 2 * (i0 + pr) + qr;
                xx = 2 * pc + qc;
                xstep = 2;
            } else {
                const int pr = p >> 6, pc = p & 63;
                yy = i0 + pr;
                xx = pc;
                xstep = 1;
            }
            float* base0 = Ybuf + ((size_t)(img * CMID + co0) * HOUT + yy) * WOUT + xx;
            float* base8 = base0 + (size_t)8 * HOUT * WOUT;
            const float v0 = acc[mt][nt][0] + bv0;
            const float v1 = acc[mt][nt][1] + bv0;
            const float v2 = acc[mt][nt][2] + bv8;
            const float v3 = acc[mt][nt][3] + bv8;
            base0[0]     = v0;
            base0[xstep] = v1;
            base8[0]     = v2;
            base8[xstep] = v3;
            tsum[mt][0] += v0 + v1;           tsq[mt][0] += v0 * v0 + v1 * v1;
            tsum[mt][1] += v2 + v3;           tsq[mt][1] += v2 * v2 + v3 * v3;
        }
    }

    // ---- deterministic partial reduction: lanes -> warps -> CTA slot ----
    __syncthreads();                           // mainloop smem now reusable
    float2* part = reinterpret_cast<float2*>(smem_c);   // [wn][128 ch] = 4KB
#pragma unroll
    for (int mt = 0; mt < 4; ++mt)
#pragma unroll
        for (int c8 = 0; c8 < 2; ++c8) {
            float s = tsum[mt][c8], q = tsq[mt][c8];
            s += __shfl_xor_sync(0xffffffffu, s, 1);
            s += __shfl_xor_sync(0xffffffffu, s, 2);
            q += __shfl_xor_sync(0xffffffffu, q, 1);
            q += __shfl_xor_sync(0xffffffffu, q, 2);
            if ((lane & 3) == 0) {
                const int chl = wm * 64 + mt * 16 + (lane >> 2) + c8 * 8;
                part[wn * 128 + chl] = make_float2(s, q);
            }
        }
    __syncthreads();
    if (tid < 128) {
        const float2 p0 = part[tid], p1 = part[128 + tid], p2 = part[256 + tid], p3 = part[384 + tid];
        const float2 r = make_float2(p0.x + p1.x + p2.x + p3.x, p0.y + p1.y + p2.y + p3.y);
        const int slot = blockIdx.x * (PHASE2 ? 512 : 128) + blockIdx.y;
        (PHASE2 ? g_part2 : g_part1)[slot * 128 + tid] = r;
    }
}

// ---------------------------------------------------------------------------
// Kernel wrappers: constexpr tap dispatch per CTA (phase 1) / fixed 3x3 (phase 2)
// ---------------------------------------------------------------------------
template <int CIN_T, int WDIM, int ROWS, int MTOT, bool PHASE2>
__global__ __launch_bounds__(256, 2)
void gemm_kernel(const float* __restrict__ bias9)
{
    constexpr int NT_PER_IMG = (WDIM * WDIM) / 128;
    extern __shared__ char smem[];
    const uint32_t sb = smem_u32(smem);

    const int tid  = threadIdx.x;
    const int wid  = tid >> 5;
    const int lane = tid & 31;
    const int m0   = blockIdx.x * 128;
    const int img  = blockIdx.y / NT_PER_IMG;
    const int i0   = (blockIdx.y % NT_PER_IMG) * ROWS;

    if (PHASE2) {
        run_gemm<3, 3, CIN_T, WDIM, ROWS, MTOT, PHASE2>(smem, sb, tid, wid, lane, m0, img, i0, bias9);
    } else {
        switch ((m0 >> 8) & 3) {   // 0:(3,3) 1:(2,3) 2:(3,2) 3:(2,2)
        case 0: run_gemm<3, 3, CIN_T, WDIM, ROWS, MTOT, PHASE2>(smem, sb, tid, wid, lane, m0, img, i0, bias9); break;
        case 1: run_gemm<2, 3, CIN_T, WDIM, ROWS, MTOT, PHASE2>(smem, sb, tid, wid, lane, m0, img, i0, bias9); break;
        case 2: run_gemm<3, 2, CIN_T, WDIM, ROWS, MTOT, PHASE2>(smem, sb, tid, wid, lane, m0, img, i0, bias9); break;
        default: run_gemm<2, 2, CIN_T, WDIM, ROWS, MTOT, PHASE2>(smem, sb, tid, wid, lane, m0, img, i0, bias9); break;
        }
    }
}

// ---------------------------------------------------------------------------
// BN finalize: reduce per-CTA partials -> folded affine (a, s).
// Y1/Y2: channel ch receives 4 convs x 128 ntiles = 512 partials.
// ---------------------------------------------------------------------------
__global__ void bn_finalize12_kernel(const float* __restrict__ gA, const float* __restrict__ beA,
                                     const float* __restrict__ gB, const float* __restrict__ beB)
{
    const int which = blockIdx.y;          // 0: Y1 (convs 0-3), 1: Y2 (convs 4-7)
    const int ch = blockIdx.x;
    const int mhalf = ch >> 7, chl = ch & 127;
    const int tid = threadIdx.x;

    float s = 0.0f, q = 0.0f;
    for (int i = tid; i < 512; i += 256) {
        const int cv = i >> 7, by = i & 127;
        const int bx = (which * 4 + cv) * 2 + mhalf;
        const float2 p = g_part1[(bx * 128 + by) * 128 + chl];
        s += p.x; q += p.y;
    }
    __shared__ float rs[256], rq[256];
    rs[tid] = s; rq[tid] = q;
    __syncthreads();
    for (int off = 128; off > 0; off >>= 1) {
        if (tid < off) { rs[tid] += rs[tid + off]; rq[tid] += rq[tid + off]; }
        __syncthreads();
    }
    if (tid == 0) {
        const float inv = 1.0f / 65536.0f;
        const float mean = rs[0] * inv;
        const float var  = rq[0] * inv - mean * mean;
        const float* gamma = which ? gB : gA;
        const float* beta  = which ? beB : beA;
        const float a = gamma[ch] * rsqrtf(var + 1e-5f);
        if (which) { g_a2[ch] = a; g_s2[ch] = beta[ch] - mean * a; }
        else       { g_a1[ch] = a; g_s1[ch] = beta[ch] - mean * a; }
    }
}

// O1: channel ch receives 512 ntile partials.
__global__ void bn_finalize2_kernel(const float* __restrict__ gamma, const float* __restrict__ beta)
{
    const int ch = blockIdx.x;
    const int bx = ch >> 7, chl = ch & 127;
    const int tid = threadIdx.x;

    float s = 0.0f, q = 0.0f;
    for (int by = tid; by < 512; by += 256) {
        const float2 p = g_part2[(bx * 512 + by) * 128 + chl];
        s += p.x; q += p.y;
    }
    __shared__ float rs[256], rq[256];
    rs[tid] = s; rq[tid] = q;
    __syncthreads();
    for (int off = 128; off > 0; off >>= 1) {
        if (tid < off) { rs[tid] += rs[tid + off]; rq[tid] += rq[tid + off]; }
        __syncthreads();
    }
    if (tid == 0) {
        const float inv = 1.0f / 65536.0f;
        const float mean = rs[0] * inv;
        const float var  = rq[0] * inv - mean * mean;
        const float a = gamma[ch] * rsqrtf(var + 1e-5f);
        g_a3[ch] = a;
        g_s3[ch] = beta[ch] - mean * a;
    }
}

// ---------------------------------------------------------------------------
// Final merge: out = relu( BN2(O1) + BN12(Y2) )
// ---------------------------------------------------------------------------
__global__ void final_kernel(float* __restrict__ out)
{
    const int idx = blockIdx.x * blockDim.x + threadIdx.x;
    if (idx >= NOUT / 4) return;
    const int c = (idx >> 10) & (CMID - 1);
    const float a2 = g_a2[c], s2 = g_s2[c];
    const float a3 = g_a3[c], s3 = g_s3[c];
    const float4 o = reinterpret_cast<const float4*>(g_O1)[idx];
    const float4 y = reinterpret_cast<const float4*>(g_Y2)[idx];
    float4 r;
    r.x = fmaxf(0.0f, fmaf(o.x, a3, s3) + fmaf(y.x, a2, s2));
    r.y = fmaxf(0.0f, fmaf(o.y, a3, s3) + fmaf(y.y, a2, s2));
    r.z = fmaxf(0.0f, fmaf(o.z, a3, s3) + fmaf(y.z, a2, s2));
    r.w = fmaxf(0.0f, fmaf(o.w, a3, s3) + fmaf(y.w, a2, s2));
    reinterpret_cast<float4*>(out)[idx] = r;
}

// ---------------------------------------------------------------------------
// Launch sequence
// ---------------------------------------------------------------------------
extern "C" void kernel_launch(void* const* d_in, const int* in_sizes, int n_in,
                              void* d_out, int out_size)
{
    const float* x   = (const float*)d_in[0];
    const float* w1  = (const float*)d_in[1];   const float* b1  = (const float*)d_in[2];
    const float* w2  = (const float*)d_in[3];   const float* b2  = (const float*)d_in[4];
    const float* w3  = (const float*)d_in[5];   const float* b3  = (const float*)d_in[6];
    const float* w4  = (const float*)d_in[7];   const float* b4  = (const float*)d_in[8];
    const float* w5  = (const float*)d_in[9];   const float* b5  = (const float*)d_in[10];
    const float* w6  = (const float*)d_in[11];  const float* b6  = (const float*)d_in[12];
    const float* w7  = (const float*)d_in[13];  const float* b7  = (const float*)d_in[14];
    const float* w8  = (const float*)d_in[15];  const float* b8  = (const float*)d_in[16];
    const float* w9  = (const float*)d_in[17];  const float* b9  = (const float*)d_in[18];
    const float* g11 = (const float*)d_in[19];  const float* be11 = (const float*)d_in[20];
    const float* g12 = (const float*)d_in[21];  const float* be12 = (const float*)d_in[22];
    const float* g2  = (const float*)d_in[23];  const float* be2  = (const float*)d_in[24];

    const int SMEM_GEMM = 3 * 32768;   // 98,304 B (3-stage pipeline, 2 CTAs/SM)
    cudaFuncSetAttribute(gemm_kernel<512, 32, 4, 2048, false>,
                         cudaFuncAttributeMaxDynamicSharedMemorySize, SMEM_GEMM);
    cudaFuncSetAttribute(gemm_kernel<256, 64, 2, 256, true>,
                         cudaFuncAttributeMaxDynamicSharedMemorySize, SMEM_GEMM);

    // Pre-passes: all weights (incl. conv9) in one launch + input transform
    const int PREP_BLOCKS = (9 * 2048 * 512 + 9 * 256 * 256 + 255) / 256;
    prep_weights_kernel<<<PREP_BLOCKS, 256>>>(w1, w2, w3, w4, w5, w6, w7, w8,
                                              b1, b2, b3, b4, b5, b6, b7, b8, w9);
    pad_transpose_kernel<512, 32, false><<<BATCH * 34 * 8, 256>>>(x);

    // Phase-1 GEMM: all 8 unpool convs; epilogue emits BN partials.
    gemm_kernel<512, 32, 4, 2048, false><<<dim3(16, 128), 256, SMEM_GEMM>>>(nullptr);

    // BN11 + BN12 finalize (reduces 2 MB of partials instead of 128 MB of Y)
    bn_finalize12_kernel<<<dim3(CMID, 2), 256>>>(g11, be11, g12, be12);

    // relu(BN11(Y1)) -> padded transposed fp16
    pad_transpose_kernel<256, 64, true><<<BATCH * 66 * 4, 256>>>(nullptr);

    // Phase-2 GEMM: conv9; epilogue emits BN partials.
    gemm_kernel<256, 64, 2, 256, true><<<dim3(2, 512), 256, SMEM_GEMM>>>(b9);

    // BN2 finalize
    bn_finalize2_kernel<<<CMID, 256>>>(g2, be2);

    final_kernel<<<(NOUT / 4 + 255) / 256, 256>>>((float*)d_out);
}